// round 3
// baseline (speedup 1.0000x reference)
#include <cuda_runtime.h>
#include <cstdint>

#define DI __device__ __forceinline__

constexpr int BATCH = 16384;
constexpr int DIMD  = 1024;
constexpr int H1v   = 256;
constexpr int H2v   = 128;
constexpr int GHv   = 64;
constexpr int NSv   = 4;
constexpr int DEv   = 2;
constexpr int DCv   = 3;
constexpr int NEv   = NSv + DCv * DEv;            // 10
constexpr int GCOL  = NEv * H1v;                  // 2560
constexpr int NCOLS = GCOL + DCv * GHv + 64;      // 2816 = 22 * 128

// smem geometry (floats)
constexpr int KCH   = 32;        // k per chunk
constexpr int SROW  = 36;        // padded row stride (144B, 16B aligned, conflict-free)
constexpr int BUFF  = 128 * SROW;               // 4608 floats per buffer
constexpr int BUFB  = BUFF * 4;                 // 18432 bytes
constexpr int SOFF_B = 2 * BUFB;                // 36864: B tiles after A tiles
constexpr int STG   = 132;                      // epilogue stage stride

__device__ float g_Wt1[(size_t)NCOLS * DIMD];   // [n][k], tf32-rounded
__device__ float g_b1[NCOLS];
__device__ float g_Wt2[(size_t)NEv * H2v * H1v];// [e][o][h], tf32-rounded
__device__ float g_b2[NEv * H2v];
__device__ float g_Y[(size_t)BATCH * NCOLS];
__device__ float g_gates[(size_t)DCv * BATCH * 8];

DI uint32_t smem_u32(const void* p) {
    uint32_t a;
    asm("{ .reg .u64 t; cvta.to.shared.u64 t, %1; cvt.u32.u64 %0, t; }" : "=r"(a) : "l"(p));
    return a;
}
DI float to_tf32(float x) {
    uint32_t r;
    asm("cvt.rna.tf32.f32 %0, %1;" : "=r"(r) : "f"(x));
    return __uint_as_float(r);
}
DI uint32_t cvt_tf32_bits(float x) {
    uint32_t r;
    asm("cvt.rna.tf32.f32 %0, %1;" : "=r"(r) : "f"(x));
    return r;
}
DI void cp16(uint32_t dst, const void* src) {
    asm volatile("cp.async.cg.shared.global [%0], [%1], 16;" :: "r"(dst), "l"(src));
}
DI void cp_commit() { asm volatile("cp.async.commit_group;" ::: "memory"); }
DI void cp_wait1()  { asm volatile("cp.async.wait_group 1;" ::: "memory"); }
DI void cp_wait0()  { asm volatile("cp.async.wait_group 0;" ::: "memory"); }

DI void mma8(float* d, const uint32_t* a, const uint32_t* b) {
    asm volatile("mma.sync.aligned.m16n8k8.row.col.f32.tf32.tf32.f32 "
                 "{%0,%1,%2,%3}, {%4,%5,%6,%7}, {%8,%9}, {%0,%1,%2,%3};"
                 : "+f"(d[0]), "+f"(d[1]), "+f"(d[2]), "+f"(d[3])
                 : "r"(a[0]), "r"(a[1]), "r"(a[2]), "r"(a[3]),
                   "r"(b[0]), "r"(b[1]));
}

// one K=32 chunk: warp tile 64x32 (4 M-tiles x 4 N-tiles of m16n8k8)
template<bool CVTA>
DI void compute_chunk(const float* __restrict__ A, const float* __restrict__ B,
                      int rA, int rB, int tg, float (&d)[4][4][4]) {
#pragma unroll
    for (int ks = 0; ks < 4; ++ks) {
        uint32_t af[4][4], bf[4][2];
#pragma unroll
        for (int mt = 0; mt < 4; ++mt)
#pragma unroll
            for (int i = 0; i < 4; ++i) {
                float v = A[(rA + mt * 16 + ((i & 1) ? 8 : 0)) * SROW +
                            ks * 8 + tg + ((i >= 2) ? 4 : 0)];
                af[mt][i] = CVTA ? cvt_tf32_bits(v) : __float_as_uint(v);
            }
#pragma unroll
        for (int nt = 0; nt < 4; ++nt)
#pragma unroll
            for (int j = 0; j < 2; ++j)
                bf[nt][j] = __float_as_uint(B[(rB + nt * 8) * SROW + ks * 8 + tg + j * 4]);
#pragma unroll
        for (int mt = 0; mt < 4; ++mt)
#pragma unroll
            for (int nt = 0; nt < 4; ++nt)
                mma8(d[mt][nt], af[mt], bf[nt]);
    }
}

// ---------------- weight packing ----------------
DI float w1_src(int n, int d, const float* sW1, const float* dW1, const float* gW1) {
    if (n < NSv * H1v) {
        int e = n >> 8, h = n & 255;
        return sW1[((size_t)e * DIMD + d) * H1v + h];
    } else if (n < GCOL) {
        int m = n - NSv * H1v, e = m >> 8, h = m & 255;
        return dW1[((size_t)e * DIMD + d) * H1v + h];
    } else if (n < GCOL + DCv * GHv) {
        int m = n - GCOL, g = m >> 6, k = m & 63;
        return gW1[((size_t)g * DIMD + d) * GHv + k];
    }
    return 0.0f;
}

__global__ void pack_w1_kernel(const float* __restrict__ sW1, const float* __restrict__ dW1,
                               const float* __restrict__ gW1, const float* __restrict__ sb1,
                               const float* __restrict__ db1, const float* __restrict__ gb1) {
    __shared__ float t[32][33];
    const int n0 = blockIdx.x * 32, d0 = blockIdx.y * 32;
    const int tx = threadIdx.x, ty = threadIdx.y;
#pragma unroll
    for (int i = 0; i < 4; ++i)
        t[ty + i * 8][tx] = to_tf32(w1_src(n0 + tx, d0 + ty + i * 8, sW1, dW1, gW1));
    __syncthreads();
#pragma unroll
    for (int i = 0; i < 4; ++i)
        g_Wt1[(size_t)(n0 + ty + i * 8) * DIMD + d0 + tx] = t[tx][ty + i * 8];
    if (blockIdx.y == 0 && ty == 0) {
        int n = n0 + tx;
        float bv;
        if (n < NSv * H1v) bv = sb1[n];
        else if (n < GCOL) bv = db1[n - NSv * H1v];
        else if (n < GCOL + DCv * GHv) bv = gb1[n - GCOL];
        else bv = 0.0f;
        g_b1[n] = bv;
    }
}

__global__ void pack_w2_kernel(const float* __restrict__ sW2, const float* __restrict__ dW2,
                               const float* __restrict__ sb2, const float* __restrict__ db2) {
    __shared__ float t[32][33];
    const int o0 = blockIdx.x * 32, h0 = blockIdx.y * 32, e = blockIdx.z;
    const int tx = threadIdx.x, ty = threadIdx.y;
#pragma unroll
    for (int i = 0; i < 4; ++i) {
        int h = h0 + ty + i * 8, o = o0 + tx;
        float v = (e < NSv) ? sW2[((size_t)e * H1v + h) * H2v + o]
                            : dW2[((size_t)(e - NSv) * H1v + h) * H2v + o];
        t[ty + i * 8][tx] = to_tf32(v);
    }
    __syncthreads();
#pragma unroll
    for (int i = 0; i < 4; ++i) {
        int o = o0 + ty + i * 8, h = h0 + tx;
        g_Wt2[((size_t)e * H2v + o) * H1v + h] = t[tx][ty + i * 8];
    }
    if (blockIdx.y == 0 && ty == 0) {
        int o = o0 + tx;
        g_b2[e * H2v + o] = (e < NSv) ? sb2[e * H2v + o] : db2[(e - NSv) * H2v + o];
    }
}

// ---------------- GEMM1: Y = relu(X @ W1cat + b1), CTA tile 128x128 ----------------
__global__ void __launch_bounds__(256, 2) gemm1_kernel(const float* __restrict__ x) {
    extern __shared__ char smem[];
    float* sA = reinterpret_cast<float*>(smem);
    float* sB = reinterpret_cast<float*>(smem + SOFF_B);
    const uint32_t sbase = smem_u32(smem);
    const int tid = threadIdx.x, wid = tid >> 5, lane = tid & 31;
    const int warpM = wid >> 2, warpN = wid & 3;
    const int g = lane >> 2, tg = lane & 3;
    const int n0 = blockIdx.x * 128, m0 = blockIdx.y * 128;  // x = N fastest (X stays L2-hot)
    const int rA = warpM * 64 + g, rB = warpN * 32 + g;

    float d[4][4][4] = {};

    auto load = [&](int buf, int ck) {
        const float* xa = x + (size_t)m0 * DIMD + ck * KCH;
        const float* wb = g_Wt1 + (size_t)n0 * DIMD + ck * KCH;
        const uint32_t da = sbase + buf * BUFB;
        const uint32_t db = sbase + SOFF_B + buf * BUFB;
#pragma unroll
        for (int it = 0; it < 4; ++it) {
            int idx = tid + it * 256, r = idx >> 3, cc = idx & 7;
            cp16(da + r * 144 + cc * 16, xa + (size_t)r * DIMD + cc * 4);
            cp16(db + r * 144 + cc * 16, wb + (size_t)r * DIMD + cc * 4);
        }
        cp_commit();
    };

    load(0, 0);
    for (int ck = 0; ck < 32; ++ck) {
        if (ck < 31) { load((ck + 1) & 1, ck + 1); cp_wait1(); }
        else cp_wait0();
        __syncthreads();
        compute_chunk<true>(sA + (ck & 1) * BUFF, sB + (ck & 1) * BUFF, rA, rB, tg, d);
        __syncthreads();
    }

    // epilogue: stage -> bias+relu -> coalesced store
    float* stage = reinterpret_cast<float*>(smem);
#pragma unroll
    for (int mt = 0; mt < 4; ++mt)
#pragma unroll
        for (int nt = 0; nt < 4; ++nt)
#pragma unroll
            for (int i = 0; i < 4; ++i) {
                int r = warpM * 64 + mt * 16 + g + ((i >= 2) ? 8 : 0);
                int cc = warpN * 32 + nt * 8 + tg * 2 + (i & 1);
                stage[r * STG + cc] = d[mt][nt][i];
            }
    __syncthreads();
    {
        const int cg = tid & 31, r0 = tid >> 5;
        const float4 b4 = *reinterpret_cast<const float4*>(g_b1 + n0 + cg * 4);
#pragma unroll
        for (int p = 0; p < 16; ++p) {
            int r = r0 + p * 8;
            const float* s = stage + r * STG + cg * 4;
            float4 v;
            v.x = fmaxf(s[0] + b4.x, 0.0f);
            v.y = fmaxf(s[1] + b4.y, 0.0f);
            v.z = fmaxf(s[2] + b4.z, 0.0f);
            v.w = fmaxf(s[3] + b4.w, 0.0f);
            *reinterpret_cast<float4*>(g_Y + (size_t)(m0 + r) * NCOLS + n0 + cg * 4) = v;
        }
    }
}

// ---------------- gates ----------------
__global__ void __launch_bounds__(256) gate_kernel(const float* __restrict__ gW2,
                                                   const float* __restrict__ gb2) {
    const int gw = (blockIdx.x * blockDim.x + threadIdx.x) >> 5;
    const int lane = threadIdx.x & 31;
    if (gw >= DCv * BATCH) return;
    const int g = gw / BATCH, b = gw % BATCH;
    const float* yr = g_Y + (size_t)b * NCOLS + GCOL + g * GHv;
    const float h0 = yr[2 * lane], h1 = yr[2 * lane + 1];
    const float* w = gW2 + (size_t)g * GHv * 6;
    float acc[6];
#pragma unroll
    for (int e = 0; e < 6; ++e)
        acc[e] = h0 * w[(2 * lane) * 6 + e] + h1 * w[(2 * lane + 1) * 6 + e];
#pragma unroll
    for (int e = 0; e < 6; ++e)
#pragma unroll
        for (int s = 16; s; s >>= 1) acc[e] += __shfl_xor_sync(0xFFFFFFFFu, acc[e], s);
    if (lane == 0) {
        float m = -1e30f;
#pragma unroll
        for (int e = 0; e < 6; ++e) { acc[e] += gb2[g * 6 + e]; m = fmaxf(m, acc[e]); }
        float s = 0.0f;
#pragma unroll
        for (int e = 0; e < 6; ++e) { acc[e] = expf(acc[e] - m); s += acc[e]; }
        const float inv = 1.0f / s;
#pragma unroll
        for (int e = 0; e < 6; ++e)
            g_gates[((size_t)g * BATCH + b) * 8 + e] = acc[e] * inv;
    }
}

// ---------------- GEMM2 + combine (flat (expert, chunk) pipeline) ----------------
__global__ void __launch_bounds__(256, 1) gemm2_kernel(float* __restrict__ out) {
    extern __shared__ char smem[];
    float* sA = reinterpret_cast<float*>(smem);
    float* sB = reinterpret_cast<float*>(smem + SOFF_B);
    float* stage = reinterpret_cast<float*>(smem + 2 * SOFF_B);  // separate region
    const uint32_t sbase = smem_u32(smem);
    const int tid = threadIdx.x, wid = tid >> 5, lane = tid & 31;
    const int warpM = wid >> 2, warpN = wid & 3;
    const int g = lane >> 2, tg = lane & 3;
    const int m0 = blockIdx.x * 128;
    const int rA = warpM * 64 + g, rB = warpN * 32 + g;

    float d[4][4][4] = {};

    auto load = [&](int buf, int idx) {
        const int e = idx >> 3, ck = idx & 7;
        const float* ya = g_Y + (size_t)m0 * NCOLS + e * H1v + ck * KCH;
        const float* wb = g_Wt2 + (size_t)e * H2v * H1v + ck * KCH;
        const uint32_t da = sbase + buf * BUFB;
        const uint32_t db = sbase + SOFF_B + buf * BUFB;
#pragma unroll
        for (int it = 0; it < 4; ++it) {
            int ii = tid + it * 256, r = ii >> 3, cc = ii & 7;
            cp16(da + r * 144 + cc * 16, ya + (size_t)r * NCOLS + cc * 4);
            cp16(db + r * 144 + cc * 16, wb + (size_t)r * H1v + cc * 4);
        }
        cp_commit();
    };

    load(0, 0);
    for (int idx = 0; idx < NEv * 8; ++idx) {
        const int e = idx >> 3, ck = idx & 7;
        if (idx < NEv * 8 - 1) { load((idx + 1) & 1, idx + 1); cp_wait1(); }
        else cp_wait0();
        __syncthreads();
        compute_chunk<true>(sA + (idx & 1) * BUFF, sB + (idx & 1) * BUFF, rA, rB, tg, d);
        __syncthreads();

        if (ck == 7) {
            // stage with bias + relu, reset acc
#pragma unroll
            for (int mt = 0; mt < 4; ++mt)
#pragma unroll
                for (int nt = 0; nt < 4; ++nt)
#pragma unroll
                    for (int i = 0; i < 4; ++i) {
                        int r = warpM * 64 + mt * 16 + g + ((i >= 2) ? 8 : 0);
                        int cc = warpN * 32 + nt * 8 + tg * 2 + (i & 1);
                        stage[r * STG + cc] = fmaxf(d[mt][nt][i] + g_b2[e * H2v + cc], 0.0f);
                        d[mt][nt][i] = 0.0f;
                    }
            __syncthreads();
            // combine: gate-weighted accumulation into out (rows exclusive per CTA)
            {
                const int rr = tid >> 5, c = (tid & 31) * 4;
#pragma unroll 1
                for (int p = 0; p < 16; ++p) {
                    const int r = p * 8 + rr;
                    const int R = m0 + r;
                    const float* s = stage + r * STG + c;
                    float4 z = make_float4(s[0], s[1], s[2], s[3]);
                    if (e < NSv) {
#pragma unroll
                        for (int gd = 0; gd < DCv; ++gd) {
                            const float w = g_gates[((size_t)gd * BATCH + R) * 8 + e];
                            float4* op = reinterpret_cast<float4*>(
                                out + ((size_t)gd * BATCH + R) * H2v + c);
                            if (e == 0) {
                                *op = make_float4(w * z.x, w * z.y, w * z.z, w * z.w);
                            } else {
                                float4 o = *op;
                                o.x += w * z.x; o.y += w * z.y;
                                o.z += w * z.z; o.w += w * z.w;
                                *op = o;
                            }
                        }
                    } else {
                        const int gd = (e - NSv) >> 1;
                        const float w = g_gates[((size_t)gd * BATCH + R) * 8 + NSv + ((e - NSv) & 1)];
                        float4* op = reinterpret_cast<float4*>(
                            out + ((size_t)gd * BATCH + R) * H2v + c);
                        float4 o = *op;
                        o.x += w * z.x; o.y += w * z.y;
                        o.z += w * z.z; o.w += w * z.w;
                        *op = o;
                    }
                }
            }
            __syncthreads();
        }
    }
}

extern "C" void kernel_launch(void* const* d_in, const int* in_sizes, int n_in,
                              void* d_out, int out_size) {
    const float *x, *sW1, *sb1, *sW2, *sb2, *dW1, *db1, *dW2, *db2, *gW1, *gb1, *gW2, *gb2;
    if (n_in >= 14 && in_sizes[1] == BATCH) {
        // dict order: x, domain_ids, sW1, sb1, sW2, sb2, dW1, db1, dW2, db2, gW1, gb1, gW2, gb2
        x   = (const float*)d_in[0];
        sW1 = (const float*)d_in[2];  sb1 = (const float*)d_in[3];
        sW2 = (const float*)d_in[4];  sb2 = (const float*)d_in[5];
        dW1 = (const float*)d_in[6];  db1 = (const float*)d_in[7];
        dW2 = (const float*)d_in[8];  db2 = (const float*)d_in[9];
        gW1 = (const float*)d_in[10]; gb1 = (const float*)d_in[11];
        gW2 = (const float*)d_in[12]; gb2 = (const float*)d_in[13];
    } else {
        // reference() signature order: x, sW1..gb2, domain_ids
        x   = (const float*)d_in[0];
        sW1 = (const float*)d_in[1];  sb1 = (const float*)d_in[2];
        sW2 = (const float*)d_in[3];  sb2 = (const float*)d_in[4];
        dW1 = (const float*)d_in[5];  db1 = (const float*)d_in[6];
        dW2 = (const float*)d_in[7];  db2 = (const float*)d_in[8];
        gW1 = (const float*)d_in[9];  gb1 = (const float*)d_in[10];
        gW2 = (const float*)d_in[11]; gb2 = (const float*)d_in[12];
    }
    float* out = (float*)d_out;

    cudaFuncSetAttribute(gemm1_kernel, cudaFuncAttributeMaxDynamicSharedMemorySize, 2 * SOFF_B);
    cudaFuncSetAttribute(gemm2_kernel, cudaFuncAttributeMaxDynamicSharedMemorySize,
                         2 * SOFF_B + 128 * STG * 4);

    pack_w1_kernel<<<dim3(NCOLS / 32, DIMD / 32), dim3(32, 8)>>>(sW1, dW1, gW1, sb1, db1, gb1);
    pack_w2_kernel<<<dim3(H2v / 32, H1v / 32, NEv), dim3(32, 8)>>>(sW2, dW2, sb2, db2);
    gemm1_kernel<<<dim3(NCOLS / 128, BATCH / 128), 256, 2 * SOFF_B>>>(x);
    gate_kernel<<<(DCv * BATCH) / 8, 256>>>(gW2, gb2);
    gemm2_kernel<<<BATCH / 128, 256, 2 * SOFF_B + 128 * STG * 4>>>(out);
}

// round 4
// speedup vs baseline: 1.1596x; 1.1596x over previous
#include <cuda_runtime.h>
#include <cstdint>

#define DI __device__ __forceinline__

constexpr int BATCH = 16384;
constexpr int DIMD  = 1024;
constexpr int H1v   = 256;
constexpr int H2v   = 128;
constexpr int GHv   = 64;
constexpr int NSv   = 4;
constexpr int DEv   = 2;
constexpr int DCv   = 3;
constexpr int NEv   = NSv + DCv * DEv;            // 10
constexpr int GCOL  = NEv * H1v;                  // 2560
constexpr int NCOLS = GCOL + DCv * GHv + 64;      // 2816 = 22 * 128

constexpr int KCH   = 32;
constexpr int SROW  = 36;                         // padded row stride (conflict-free)
constexpr int BUFF  = 128 * SROW;                 // floats per operand buffer
constexpr int BUFB  = BUFF * 4;                   // 18432 B
constexpr int SOFF_B = 2 * BUFB;                  // B tiles after both A stages
constexpr int SMEM_TOT = 4 * BUFB;                // 73728 B
constexpr int STG   = 132;

__device__ float g_X[(size_t)BATCH * DIMD];        // tf32-rounded input
__device__ float g_Wt1[(size_t)NCOLS * DIMD];      // [n][k] tf32
__device__ float g_b1[NCOLS];
__device__ float g_Wt2[(size_t)NEv * H2v * H1v];   // [e][o][h] tf32
__device__ float g_b2[NEv * H2v];
__device__ float g_Y[(size_t)BATCH * NCOLS];       // tf32-rounded activations
__device__ float g_Z[(size_t)NEv * BATCH * H2v];   // per-expert layer-2 out
__device__ float g_gates[(size_t)DCv * BATCH * 8];

DI uint32_t smem_u32(const void* p) {
    uint32_t a;
    asm("{ .reg .u64 t; cvta.to.shared.u64 t, %1; cvt.u32.u64 %0, t; }" : "=r"(a) : "l"(p));
    return a;
}
DI float to_tf32(float x) {
    uint32_t r;
    asm("cvt.rna.tf32.f32 %0, %1;" : "=r"(r) : "f"(x));
    return __uint_as_float(r);
}
DI void cp16(uint32_t dst, const void* src) {
    asm volatile("cp.async.cg.shared.global [%0], [%1], 16;" :: "r"(dst), "l"(src));
}
DI void cp_commit() { asm volatile("cp.async.commit_group;" ::: "memory"); }
DI void cp_wait0()  { asm volatile("cp.async.wait_group 0;" ::: "memory"); }

DI void mma8(float* d, const uint32_t* a, const uint32_t* b) {
    asm volatile("mma.sync.aligned.m16n8k8.row.col.f32.tf32.tf32.f32 "
                 "{%0,%1,%2,%3}, {%4,%5,%6,%7}, {%8,%9}, {%0,%1,%2,%3};"
                 : "+f"(d[0]), "+f"(d[1]), "+f"(d[2]), "+f"(d[3])
                 : "r"(a[0]), "r"(a[1]), "r"(a[2]), "r"(a[3]),
                   "r"(b[0]), "r"(b[1]));
}

// one K=32 chunk: warp tile 64x32 (4 M x 4 N of m16n8k8)
DI void compute_chunk(const float* __restrict__ A, const float* __restrict__ B,
                      int rA, int rB, int tg, float (&d)[4][4][4]) {
#pragma unroll
    for (int ks = 0; ks < 4; ++ks) {
        uint32_t af[4][4], bf[4][2];
#pragma unroll
        for (int mt = 0; mt < 4; ++mt)
#pragma unroll
            for (int i = 0; i < 4; ++i)
                af[mt][i] = __float_as_uint(
                    A[(rA + mt * 16 + ((i & 1) ? 8 : 0)) * SROW +
                      ks * 8 + tg + ((i >= 2) ? 4 : 0)]);
#pragma unroll
        for (int nt = 0; nt < 4; ++nt)
#pragma unroll
            for (int j = 0; j < 2; ++j)
                bf[nt][j] = __float_as_uint(B[(rB + nt * 8) * SROW + ks * 8 + tg + j * 4]);
#pragma unroll
        for (int mt = 0; mt < 4; ++mt)
#pragma unroll
            for (int nt = 0; nt < 4; ++nt)
                mma8(d[mt][nt], af[mt], bf[nt]);
    }
}

// ---------------- input rounding ----------------
__global__ void cvt_x_kernel(const float* __restrict__ x) {
    const size_t i = ((size_t)blockIdx.x * blockDim.x + threadIdx.x) * 4;
    float4 v = *reinterpret_cast<const float4*>(x + i);
    v.x = to_tf32(v.x); v.y = to_tf32(v.y); v.z = to_tf32(v.z); v.w = to_tf32(v.w);
    *reinterpret_cast<float4*>(g_X + i) = v;
}

// ---------------- weight packing ----------------
DI float w1_src(int n, int d, const float* sW1, const float* dW1, const float* gW1) {
    if (n < NSv * H1v) {
        int e = n >> 8, h = n & 255;
        return sW1[((size_t)e * DIMD + d) * H1v + h];
    } else if (n < GCOL) {
        int m = n - NSv * H1v, e = m >> 8, h = m & 255;
        return dW1[((size_t)e * DIMD + d) * H1v + h];
    } else if (n < GCOL + DCv * GHv) {
        int m = n - GCOL, g = m >> 6, k = m & 63;
        return gW1[((size_t)g * DIMD + d) * GHv + k];
    }
    return 0.0f;
}

__global__ void pack_w1_kernel(const float* __restrict__ sW1, const float* __restrict__ dW1,
                               const float* __restrict__ gW1, const float* __restrict__ sb1,
                               const float* __restrict__ db1, const float* __restrict__ gb1) {
    __shared__ float t[32][33];
    const int n0 = blockIdx.x * 32, d0 = blockIdx.y * 32;
    const int tx = threadIdx.x, ty = threadIdx.y;
#pragma unroll
    for (int i = 0; i < 4; ++i)
        t[ty + i * 8][tx] = to_tf32(w1_src(n0 + tx, d0 + ty + i * 8, sW1, dW1, gW1));
    __syncthreads();
#pragma unroll
    for (int i = 0; i < 4; ++i)
        g_Wt1[(size_t)(n0 + ty + i * 8) * DIMD + d0 + tx] = t[tx][ty + i * 8];
    if (blockIdx.y == 0 && ty == 0) {
        int n = n0 + tx;
        float bv;
        if (n < NSv * H1v) bv = sb1[n];
        else if (n < GCOL) bv = db1[n - NSv * H1v];
        else if (n < GCOL + DCv * GHv) bv = gb1[n - GCOL];
        else bv = 0.0f;
        g_b1[n] = bv;
    }
}

__global__ void pack_w2_kernel(const float* __restrict__ sW2, const float* __restrict__ dW2,
                               const float* __restrict__ sb2, const float* __restrict__ db2) {
    __shared__ float t[32][33];
    const int o0 = blockIdx.x * 32, h0 = blockIdx.y * 32, e = blockIdx.z;
    const int tx = threadIdx.x, ty = threadIdx.y;
#pragma unroll
    for (int i = 0; i < 4; ++i) {
        int h = h0 + ty + i * 8, o = o0 + tx;
        float v = (e < NSv) ? sW2[((size_t)e * H1v + h) * H2v + o]
                            : dW2[((size_t)(e - NSv) * H1v + h) * H2v + o];
        t[ty + i * 8][tx] = to_tf32(v);
    }
    __syncthreads();
#pragma unroll
    for (int i = 0; i < 4; ++i) {
        int o = o0 + ty + i * 8, h = h0 + tx;
        g_Wt2[((size_t)e * H2v + o) * H1v + h] = t[tx][ty + i * 8];
    }
    if (blockIdx.y == 0 && ty == 0) {
        int o = o0 + tx;
        g_b2[e * H2v + o] = (e < NSv) ? sb2[e * H2v + o] : db2[(e - NSv) * H2v + o];
    }
}

// ---------------- GEMM1: Y = tf32(relu(X @ W1cat + b1)) ----------------
__global__ void __launch_bounds__(256, 2) gemm1_kernel() {
    extern __shared__ char smem[];
    float* sA = reinterpret_cast<float*>(smem);
    float* sB = reinterpret_cast<float*>(smem + SOFF_B);
    const uint32_t sbase = smem_u32(smem);
    const int tid = threadIdx.x, wid = tid >> 5, lane = tid & 31;
    const int warpM = wid >> 2, warpN = wid & 3;
    const int g = lane >> 2, tg = lane & 3;
    const int n0 = blockIdx.x * 128, m0 = blockIdx.y * 128;   // N fastest -> X L2-hot
    const int rA = warpM * 64 + g, rB = warpN * 32 + g;

    float d[4][4][4] = {};

    auto load = [&](int buf, int ck) {
        const float* xa = g_X + (size_t)m0 * DIMD + ck * KCH;
        const float* wb = g_Wt1 + (size_t)n0 * DIMD + ck * KCH;
        const uint32_t da = sbase + buf * BUFB;
        const uint32_t db = sbase + SOFF_B + buf * BUFB;
#pragma unroll
        for (int it = 0; it < 4; ++it) {
            int idx = tid + it * 256, r = idx >> 3, cc = idx & 7;
            cp16(da + r * 144 + cc * 16, xa + (size_t)r * DIMD + cc * 4);
            cp16(db + r * 144 + cc * 16, wb + (size_t)r * DIMD + cc * 4);
        }
        cp_commit();
    };

    load(0, 0);
    for (int ck = 0; ck < 32; ++ck) {
        cp_wait0();
        __syncthreads();
        if (ck < 31) load((ck + 1) & 1, ck + 1);
        compute_chunk(sA + (ck & 1) * BUFF, sB + (ck & 1) * BUFF, rA, rB, tg, d);
    }
    __syncthreads();

    float* stage = reinterpret_cast<float*>(smem);
#pragma unroll
    for (int mt = 0; mt < 4; ++mt)
#pragma unroll
        for (int nt = 0; nt < 4; ++nt)
#pragma unroll
            for (int i = 0; i < 4; ++i) {
                int r = warpM * 64 + mt * 16 + g + ((i >= 2) ? 8 : 0);
                int cc = warpN * 32 + nt * 8 + tg * 2 + (i & 1);
                stage[r * STG + cc] = d[mt][nt][i];
            }
    __syncthreads();
    {
        const int cg = tid & 31, r0 = tid >> 5;
        const float4 b4 = *reinterpret_cast<const float4*>(g_b1 + n0 + cg * 4);
#pragma unroll
        for (int p = 0; p < 16; ++p) {
            int r = r0 + p * 8;
            const float* s = stage + r * STG + cg * 4;
            float4 v;
            v.x = to_tf32(fmaxf(s[0] + b4.x, 0.0f));
            v.y = to_tf32(fmaxf(s[1] + b4.y, 0.0f));
            v.z = to_tf32(fmaxf(s[2] + b4.z, 0.0f));
            v.w = to_tf32(fmaxf(s[3] + b4.w, 0.0f));
            *reinterpret_cast<float4*>(g_Y + (size_t)(m0 + r) * NCOLS + n0 + cg * 4) = v;
        }
    }
}

// ---------------- gates ----------------
__global__ void __launch_bounds__(256) gate_kernel(const float* __restrict__ gW2,
                                                   const float* __restrict__ gb2) {
    const int gw = (blockIdx.x * blockDim.x + threadIdx.x) >> 5;
    const int lane = threadIdx.x & 31;
    if (gw >= DCv * BATCH) return;
    const int g = gw / BATCH, b = gw % BATCH;
    const float* yr = g_Y + (size_t)b * NCOLS + GCOL + g * GHv;
    const float h0 = yr[2 * lane], h1 = yr[2 * lane + 1];
    const float* w = gW2 + (size_t)g * GHv * 6;
    float acc[6];
#pragma unroll
    for (int e = 0; e < 6; ++e)
        acc[e] = h0 * w[(2 * lane) * 6 + e] + h1 * w[(2 * lane + 1) * 6 + e];
#pragma unroll
    for (int e = 0; e < 6; ++e)
#pragma unroll
        for (int s = 16; s; s >>= 1) acc[e] += __shfl_xor_sync(0xFFFFFFFFu, acc[e], s);
    if (lane == 0) {
        float m = -1e30f;
#pragma unroll
        for (int e = 0; e < 6; ++e) { acc[e] += gb2[g * 6 + e]; m = fmaxf(m, acc[e]); }
        float s = 0.0f;
#pragma unroll
        for (int e = 0; e < 6; ++e) { acc[e] = expf(acc[e] - m); s += acc[e]; }
        const float inv = 1.0f / s;
#pragma unroll
        for (int e = 0; e < 6; ++e)
            g_gates[((size_t)g * BATCH + b) * 8 + e] = acc[e] * inv;
    }
}

// ---------------- GEMM2: Z[e] = relu(Y_e @ W2_e + b2_e), grid (m, e) ----------------
__global__ void __launch_bounds__(256, 2) gemm2_kernel() {
    extern __shared__ char smem[];
    float* sA = reinterpret_cast<float*>(smem);
    float* sB = reinterpret_cast<float*>(smem + SOFF_B);
    const uint32_t sbase = smem_u32(smem);
    const int tid = threadIdx.x, wid = tid >> 5, lane = tid & 31;
    const int warpM = wid >> 2, warpN = wid & 3;
    const int g = lane >> 2, tg = lane & 3;
    const int m0 = blockIdx.x * 128, e = blockIdx.y;
    const int rA = warpM * 64 + g, rB = warpN * 32 + g;

    float d[4][4][4] = {};

    auto load = [&](int buf, int ck) {
        const float* ya = g_Y + (size_t)m0 * NCOLS + e * H1v + ck * KCH;
        const float* wb = g_Wt2 + (size_t)e * H2v * H1v + ck * KCH;
        const uint32_t da = sbase + buf * BUFB;
        const uint32_t db = sbase + SOFF_B + buf * BUFB;
#pragma unroll
        for (int it = 0; it < 4; ++it) {
            int ii = tid + it * 256, r = ii >> 3, cc = ii & 7;
            cp16(da + r * 144 + cc * 16, ya + (size_t)r * NCOLS + cc * 4);
            cp16(db + r * 144 + cc * 16, wb + (size_t)r * H1v + cc * 4);
        }
        cp_commit();
    };

    load(0, 0);
    for (int ck = 0; ck < 8; ++ck) {
        cp_wait0();
        __syncthreads();
        if (ck < 7) load((ck + 1) & 1, ck + 1);
        compute_chunk(sA + (ck & 1) * BUFF, sB + (ck & 1) * BUFF, rA, rB, tg, d);
    }
    __syncthreads();

    float* stage = reinterpret_cast<float*>(smem);
#pragma unroll
    for (int mt = 0; mt < 4; ++mt)
#pragma unroll
        for (int nt = 0; nt < 4; ++nt)
#pragma unroll
            for (int i = 0; i < 4; ++i) {
                int r = warpM * 64 + mt * 16 + g + ((i >= 2) ? 8 : 0);
                int cc = warpN * 32 + nt * 8 + tg * 2 + (i & 1);
                stage[r * STG + cc] = d[mt][nt][i];
            }
    __syncthreads();
    {
        const int cg = tid & 31, r0 = tid >> 5;
        const float4 b4 = *reinterpret_cast<const float4*>(g_b2 + e * H2v + cg * 4);
#pragma unroll
        for (int p = 0; p < 16; ++p) {
            int r = r0 + p * 8;
            const float* s = stage + r * STG + cg * 4;
            float4 v;
            v.x = fmaxf(s[0] + b4.x, 0.0f);
            v.y = fmaxf(s[1] + b4.y, 0.0f);
            v.z = fmaxf(s[2] + b4.z, 0.0f);
            v.w = fmaxf(s[3] + b4.w, 0.0f);
            *reinterpret_cast<float4*>(g_Z + ((size_t)e * BATCH + m0 + r) * H2v + cg * 4) = v;
        }
    }
}

// ---------------- combine: out[g,b,:] = sum_e gates[g,b,e] * Z[e,b,:] ----------------
__global__ void __launch_bounds__(256) combine_kernel(float* __restrict__ out) {
    const int gid = blockIdx.x * blockDim.x + threadIdx.x;
    const int b = gid >> 5, c = (gid & 31) * 4;
    if (b >= BATCH) return;
    float gw[DCv][6];
#pragma unroll
    for (int g = 0; g < DCv; ++g)
#pragma unroll
        for (int e = 0; e < 6; ++e)
            gw[g][e] = g_gates[((size_t)g * BATCH + b) * 8 + e];
    float4 acc[DCv];
#pragma unroll
    for (int g = 0; g < DCv; ++g) acc[g] = make_float4(0.f, 0.f, 0.f, 0.f);
#pragma unroll
    for (int e = 0; e < NEv; ++e) {
        float4 z = *reinterpret_cast<const float4*>(g_Z + ((size_t)e * BATCH + b) * H2v + c);
        if (e < NSv) {
#pragma unroll
            for (int g = 0; g < DCv; ++g) {
                const float w = gw[g][e];
                acc[g].x += w * z.x; acc[g].y += w * z.y;
                acc[g].z += w * z.z; acc[g].w += w * z.w;
            }
        } else {
            const int g = (e - NSv) >> 1;
            const float w = gw[g][NSv + ((e - NSv) & 1)];
            acc[g].x += w * z.x; acc[g].y += w * z.y;
            acc[g].z += w * z.z; acc[g].w += w * z.w;
        }
    }
#pragma unroll
    for (int g = 0; g < DCv; ++g)
        *reinterpret_cast<float4*>(out + ((size_t)g * BATCH + b) * H2v + c) = acc[g];
}

extern "C" void kernel_launch(void* const* d_in, const int* in_sizes, int n_in,
                              void* d_out, int out_size) {
    const float *x, *sW1, *sb1, *sW2, *sb2, *dW1, *db1, *dW2, *db2, *gW1, *gb1, *gW2, *gb2;
    if (n_in >= 14 && in_sizes[1] == BATCH) {
        x   = (const float*)d_in[0];
        sW1 = (const float*)d_in[2];  sb1 = (const float*)d_in[3];
        sW2 = (const float*)d_in[4];  sb2 = (const float*)d_in[5];
        dW1 = (const float*)d_in[6];  db1 = (const float*)d_in[7];
        dW2 = (const float*)d_in[8];  db2 = (const float*)d_in[9];
        gW1 = (const float*)d_in[10]; gb1 = (const float*)d_in[11];
        gW2 = (const float*)d_in[12]; gb2 = (const float*)d_in[13];
    } else {
        x   = (const float*)d_in[0];
        sW1 = (const float*)d_in[1];  sb1 = (const float*)d_in[2];
        sW2 = (const float*)d_in[3];  sb2 = (const float*)d_in[4];
        dW1 = (const float*)d_in[5];  db1 = (const float*)d_in[6];
        dW2 = (const float*)d_in[7];  db2 = (const float*)d_in[8];
        gW1 = (const float*)d_in[9];  gb1 = (const float*)d_in[10];
        gW2 = (const float*)d_in[11]; gb2 = (const float*)d_in[12];
    }
    float* out = (float*)d_out;

    cudaFuncSetAttribute(gemm1_kernel, cudaFuncAttributeMaxDynamicSharedMemorySize, SMEM_TOT);
    cudaFuncSetAttribute(gemm2_kernel, cudaFuncAttributeMaxDynamicSharedMemorySize, SMEM_TOT);

    cvt_x_kernel<<<(BATCH * DIMD / 4) / 256, 256>>>(x);
    pack_w1_kernel<<<dim3(NCOLS / 32, DIMD / 32), dim3(32, 8)>>>(sW1, dW1, gW1, sb1, db1, gb1);
    pack_w2_kernel<<<dim3(H2v / 32, H1v / 32, NEv), dim3(32, 8)>>>(sW2, dW2, sb2, db2);
    gemm1_kernel<<<dim3(NCOLS / 128, BATCH / 128), 256, SMEM_TOT>>>();
    gate_kernel<<<(DCv * BATCH) / 8, 256>>>(gW2, gb2);
    gemm2_kernel<<<dim3(BATCH / 128, NEv), 256, SMEM_TOT>>>();
    combine_kernel<<<(BATCH * 32) / 256, 256>>>(out);
}

// round 5
// speedup vs baseline: 1.2603x; 1.0869x over previous
#include <cuda_runtime.h>
#include <cstdint>

#define DI __device__ __forceinline__

constexpr int BATCH = 16384;
constexpr int DIMD  = 1024;
constexpr int H1v   = 256;
constexpr int H2v   = 128;
constexpr int GHv   = 64;
constexpr int NSv   = 4;
constexpr int DEv   = 2;
constexpr int DCv   = 3;
constexpr int NEv   = NSv + DCv * DEv;            // 10
constexpr int GCOL  = NEv * H1v;                  // 2560
constexpr int NCOLS = GCOL + DCv * GHv + 64;      // 2816 = 22 * 128

constexpr int KCH   = 32;
constexpr int SROW  = 36;                         // padded row stride (conflict-free)
constexpr int BUFF  = 128 * SROW;                 // floats per operand buffer
constexpr int BUFB  = BUFF * 4;                   // 18432 B
constexpr int SOFF_B = 2 * BUFB;
constexpr int SMEM_TOT = 4 * BUFB;                // 73728 B
constexpr int STG   = 132;

__device__ float g_X[(size_t)BATCH * DIMD];
__device__ float g_Wt1[(size_t)NCOLS * DIMD];      // [n][k] tf32
__device__ float g_b1[NCOLS];
__device__ float g_Wt2[(size_t)NEv * H2v * H1v];   // [e][o][h] tf32
__device__ float g_b2[NEv * H2v];
__device__ float g_Y[(size_t)BATCH * NCOLS];       // tf32-rounded activations
__device__ float g_Z[(size_t)NEv * BATCH * H2v];
__device__ float g_gates[(size_t)DCv * BATCH * 8];

DI uint32_t smem_u32(const void* p) {
    uint32_t a;
    asm("{ .reg .u64 t; cvta.to.shared.u64 t, %1; cvt.u32.u64 %0, t; }" : "=r"(a) : "l"(p));
    return a;
}
DI float to_tf32(float x) {
    uint32_t r;
    asm("cvt.rna.tf32.f32 %0, %1;" : "=r"(r) : "f"(x));
    return __uint_as_float(r);
}
DI void cp16(uint32_t dst, const void* src) {
    asm volatile("cp.async.cg.shared.global [%0], [%1], 16;" :: "r"(dst), "l"(src));
}
DI void cp_commit() { asm volatile("cp.async.commit_group;" ::: "memory"); }
DI void cp_wait0()  { asm volatile("cp.async.wait_group 0;" ::: "memory"); }

DI void mma8(float* d, const uint32_t* a, const uint32_t* b) {
    asm volatile("mma.sync.aligned.m16n8k8.row.col.f32.tf32.tf32.f32 "
                 "{%0,%1,%2,%3}, {%4,%5,%6,%7}, {%8,%9}, {%0,%1,%2,%3};"
                 : "+f"(d[0]), "+f"(d[1]), "+f"(d[2]), "+f"(d[3])
                 : "r"(a[0]), "r"(a[1]), "r"(a[2]), "r"(a[3]),
                   "r"(b[0]), "r"(b[1]));
}
DI void ldm4(uint32_t* r, uint32_t addr) {
    asm volatile("ldmatrix.sync.aligned.m8n8.x4.shared.b16 {%0,%1,%2,%3}, [%4];"
                 : "=r"(r[0]), "=r"(r[1]), "=r"(r[2]), "=r"(r[3]) : "r"(addr));
}

// warp tile 64x64: per ks-group 8 ldmatrix.x4 + 32 mma
DI void compute_chunk64(uint32_t aB, uint32_t bB,
                        const uint32_t* aoff, const uint32_t* boff,
                        float (&d)[4][8][4]) {
#pragma unroll
    for (int ks = 0; ks < 4; ++ks) {
        uint32_t a[4][4], b[4][4];
#pragma unroll
        for (int mt = 0; mt < 4; ++mt) ldm4(a[mt], aB + aoff[mt] + ks * 32);
#pragma unroll
        for (int p = 0; p < 4; ++p)  ldm4(b[p], bB + boff[p] + ks * 32);
#pragma unroll
        for (int mt = 0; mt < 4; ++mt)
#pragma unroll
            for (int p = 0; p < 4; ++p) {
                mma8(d[mt][2 * p],     a[mt], &b[p][0]);
                mma8(d[mt][2 * p + 1], a[mt], &b[p][2]);
            }
    }
}

// lane-constant ldmatrix offsets (bytes, relative to operand buffer base)
// A tiles (per mt): t0 rows+0 k0, t1 rows+8 k0, t2 rows+0 k4, t3 rows+8 k4 -> a0..a3
DI void make_aoff(uint32_t* aoff, int warpM, int lane) {
    const int lr = lane & 7, lq = (lane >> 3) & 1, lp = (lane >> 4) & 1;
#pragma unroll
    for (int mt = 0; mt < 4; ++mt)
        aoff[mt] = ((warpM * 64 + mt * 16 + lq * 8 + lr) * SROW + lp * 4) * 4;
}
// B tiles (per nt-pair p): t0 n+0 k0, t1 n+0 k4, t2 n+8 k0, t3 n+8 k4 -> b0e,b1e,b0o,b1o
DI void make_boff(uint32_t* boff, int warpN, int lane) {
    const int lr = lane & 7, lq = (lane >> 3) & 1, lp = (lane >> 4) & 1;
#pragma unroll
    for (int p = 0; p < 4; ++p)
        boff[p] = ((warpN * 64 + p * 16 + lp * 8 + lr) * SROW + lq * 4) * 4;
}

// ---------------- input rounding ----------------
__global__ void cvt_x_kernel(const float* __restrict__ x) {
    const size_t i = ((size_t)blockIdx.x * blockDim.x + threadIdx.x) * 4;
    float4 v = *reinterpret_cast<const float4*>(x + i);
    v.x = to_tf32(v.x); v.y = to_tf32(v.y); v.z = to_tf32(v.z); v.w = to_tf32(v.w);
    *reinterpret_cast<float4*>(g_X + i) = v;
}

// ---------------- weight packing ----------------
DI float w1_src(int n, int d, const float* sW1, const float* dW1, const float* gW1) {
    if (n < NSv * H1v) {
        int e = n >> 8, h = n & 255;
        return sW1[((size_t)e * DIMD + d) * H1v + h];
    } else if (n < GCOL) {
        int m = n - NSv * H1v, e = m >> 8, h = m & 255;
        return dW1[((size_t)e * DIMD + d) * H1v + h];
    } else if (n < GCOL + DCv * GHv) {
        int m = n - GCOL, g = m >> 6, k = m & 63;
        return gW1[((size_t)g * DIMD + d) * GHv + k];
    }
    return 0.0f;
}

__global__ void pack_w1_kernel(const float* __restrict__ sW1, const float* __restrict__ dW1,
                               const float* __restrict__ gW1, const float* __restrict__ sb1,
                               const float* __restrict__ db1, const float* __restrict__ gb1) {
    __shared__ float t[32][33];
    const int n0 = blockIdx.x * 32, d0 = blockIdx.y * 32;
    const int tx = threadIdx.x, ty = threadIdx.y;
#pragma unroll
    for (int i = 0; i < 4; ++i)
        t[ty + i * 8][tx] = to_tf32(w1_src(n0 + tx, d0 + ty + i * 8, sW1, dW1, gW1));
    __syncthreads();
#pragma unroll
    for (int i = 0; i < 4; ++i)
        g_Wt1[(size_t)(n0 + ty + i * 8) * DIMD + d0 + tx] = t[tx][ty + i * 8];
    if (blockIdx.y == 0 && ty == 0) {
        int n = n0 + tx;
        float bv;
        if (n < NSv * H1v) bv = sb1[n];
        else if (n < GCOL) bv = db1[n - NSv * H1v];
        else if (n < GCOL + DCv * GHv) bv = gb1[n - GCOL];
        else bv = 0.0f;
        g_b1[n] = bv;
    }
}

__global__ void pack_w2_kernel(const float* __restrict__ sW2, const float* __restrict__ dW2,
                               const float* __restrict__ sb2, const float* __restrict__ db2) {
    __shared__ float t[32][33];
    const int o0 = blockIdx.x * 32, h0 = blockIdx.y * 32, e = blockIdx.z;
    const int tx = threadIdx.x, ty = threadIdx.y;
#pragma unroll
    for (int i = 0; i < 4; ++i) {
        int h = h0 + ty + i * 8, o = o0 + tx;
        float v = (e < NSv) ? sW2[((size_t)e * H1v + h) * H2v + o]
                            : dW2[((size_t)(e - NSv) * H1v + h) * H2v + o];
        t[ty + i * 8][tx] = to_tf32(v);
    }
    __syncthreads();
#pragma unroll
    for (int i = 0; i < 4; ++i) {
        int o = o0 + ty + i * 8, h = h0 + tx;
        g_Wt2[((size_t)e * H2v + o) * H1v + h] = t[tx][ty + i * 8];
    }
    if (blockIdx.y == 0 && ty == 0) {
        int o = o0 + tx;
        g_b2[e * H2v + o] = (e < NSv) ? sb2[e * H2v + o] : db2[(e - NSv) * H2v + o];
    }
}

// ---------------- GEMM1: Y = tf32(relu(X @ W1cat + b1)), 128 threads, 4 warps 64x64 ----------------
__global__ void __launch_bounds__(128, 2) gemm1_kernel() {
    extern __shared__ char smem[];
    const uint32_t sbase = smem_u32(smem);
    const int tid = threadIdx.x, wid = tid >> 5, lane = tid & 31;
    const int warpM = wid >> 1, warpN = wid & 1;
    const int g = lane >> 2, tg = lane & 3;
    const int n0 = blockIdx.x * 128, m0 = blockIdx.y * 128;   // N fastest -> X L2-hot

    uint32_t aoff[4], boff[4];
    make_aoff(aoff, warpM, lane);
    make_boff(boff, warpN, lane);

    float d[4][8][4] = {};

    auto load = [&](int buf, int ck) {
        const float* xa = g_X + (size_t)m0 * DIMD + ck * KCH;
        const float* wb = g_Wt1 + (size_t)n0 * DIMD + ck * KCH;
        const uint32_t da = sbase + buf * BUFB;
        const uint32_t db = sbase + SOFF_B + buf * BUFB;
#pragma unroll
        for (int it = 0; it < 8; ++it) {
            int idx = tid + it * 128, r = idx >> 3, cc = idx & 7;
            cp16(da + r * 144 + cc * 16, xa + (size_t)r * DIMD + cc * 4);
            cp16(db + r * 144 + cc * 16, wb + (size_t)r * DIMD + cc * 4);
        }
        cp_commit();
    };

    load(0, 0);
    for (int ck = 0; ck < 32; ++ck) {
        cp_wait0();
        __syncthreads();
        if (ck < 31) load((ck + 1) & 1, ck + 1);
        const int buf = ck & 1;
        compute_chunk64(sbase + buf * BUFB, sbase + SOFF_B + buf * BUFB, aoff, boff, d);
        __syncthreads();
    }

    float* stage = reinterpret_cast<float*>(smem);
#pragma unroll
    for (int mt = 0; mt < 4; ++mt)
#pragma unroll
        for (int nt = 0; nt < 8; ++nt)
#pragma unroll
            for (int i = 0; i < 4; ++i) {
                int r = warpM * 64 + mt * 16 + g + ((i >= 2) ? 8 : 0);
                int cc = warpN * 64 + nt * 8 + tg * 2 + (i & 1);
                stage[r * STG + cc] = d[mt][nt][i];
            }
    __syncthreads();
    {
        const int cg = tid & 31, r0 = tid >> 5;
        const float4 b4 = *reinterpret_cast<const float4*>(g_b1 + n0 + cg * 4);
#pragma unroll
        for (int p = 0; p < 32; ++p) {
            int r = r0 + p * 4;
            const float* s = stage + r * STG + cg * 4;
            float4 v;
            v.x = to_tf32(fmaxf(s[0] + b4.x, 0.0f));
            v.y = to_tf32(fmaxf(s[1] + b4.y, 0.0f));
            v.z = to_tf32(fmaxf(s[2] + b4.z, 0.0f));
            v.w = to_tf32(fmaxf(s[3] + b4.w, 0.0f));
            *reinterpret_cast<float4*>(g_Y + (size_t)(m0 + r) * NCOLS + n0 + cg * 4) = v;
        }
    }
}

// ---------------- gates ----------------
__global__ void __launch_bounds__(256) gate_kernel(const float* __restrict__ gW2,
                                                   const float* __restrict__ gb2) {
    const int gw = (blockIdx.x * blockDim.x + threadIdx.x) >> 5;
    const int lane = threadIdx.x & 31;
    if (gw >= DCv * BATCH) return;
    const int g = gw / BATCH, b = gw % BATCH;
    const float* yr = g_Y + (size_t)b * NCOLS + GCOL + g * GHv;
    const float h0 = yr[2 * lane], h1 = yr[2 * lane + 1];
    const float* w = gW2 + (size_t)g * GHv * 6;
    float acc[6];
#pragma unroll
    for (int e = 0; e < 6; ++e)
        acc[e] = h0 * w[(2 * lane) * 6 + e] + h1 * w[(2 * lane + 1) * 6 + e];
#pragma unroll
    for (int e = 0; e < 6; ++e)
#pragma unroll
        for (int s = 16; s; s >>= 1) acc[e] += __shfl_xor_sync(0xFFFFFFFFu, acc[e], s);
    if (lane == 0) {
        float m = -1e30f;
#pragma unroll
        for (int e = 0; e < 6; ++e) { acc[e] += gb2[g * 6 + e]; m = fmaxf(m, acc[e]); }
        float s = 0.0f;
#pragma unroll
        for (int e = 0; e < 6; ++e) { acc[e] = expf(acc[e] - m); s += acc[e]; }
        const float inv = 1.0f / s;
#pragma unroll
        for (int e = 0; e < 6; ++e)
            g_gates[((size_t)g * BATCH + b) * 8 + e] = acc[e] * inv;
    }
}

// ---------------- GEMM2: Z[e] = relu(Y_e @ W2_e + b2_e), grid (m, e) ----------------
__global__ void __launch_bounds__(128, 2) gemm2_kernel() {
    extern __shared__ char smem[];
    const uint32_t sbase = smem_u32(smem);
    const int tid = threadIdx.x, wid = tid >> 5, lane = tid & 31;
    const int warpM = wid >> 1, warpN = wid & 1;
    const int g = lane >> 2, tg = lane & 3;
    const int m0 = blockIdx.x * 128, e = blockIdx.y;

    uint32_t aoff[4], boff[4];
    make_aoff(aoff, warpM, lane);
    make_boff(boff, warpN, lane);

    float d[4][8][4] = {};

    auto load = [&](int buf, int ck) {
        const float* ya = g_Y + (size_t)m0 * NCOLS + e * H1v + ck * KCH;
        const float* wb = g_Wt2 + (size_t)e * H2v * H1v + ck * KCH;
        const uint32_t da = sbase + buf * BUFB;
        const uint32_t db = sbase + SOFF_B + buf * BUFB;
#pragma unroll
        for (int it = 0; it < 8; ++it) {
            int ii = tid + it * 128, r = ii >> 3, cc = ii & 7;
            cp16(da + r * 144 + cc * 16, ya + (size_t)r * NCOLS + cc * 4);
            cp16(db + r * 144 + cc * 16, wb + (size_t)r * H1v + cc * 4);
        }
        cp_commit();
    };

    load(0, 0);
    for (int ck = 0; ck < 8; ++ck) {
        cp_wait0();
        __syncthreads();
        if (ck < 7) load((ck + 1) & 1, ck + 1);
        const int buf = ck & 1;
        compute_chunk64(sbase + buf * BUFB, sbase + SOFF_B + buf * BUFB, aoff, boff, d);
        __syncthreads();
    }

    float* stage = reinterpret_cast<float*>(smem);
#pragma unroll
    for (int mt = 0; mt < 4; ++mt)
#pragma unroll
        for (int nt = 0; nt < 8; ++nt)
#pragma unroll
            for (int i = 0; i < 4; ++i) {
                int r = warpM * 64 + mt * 16 + g + ((i >= 2) ? 8 : 0);
                int cc = warpN * 64 + nt * 8 + tg * 2 + (i & 1);
                stage[r * STG + cc] = d[mt][nt][i];
            }
    __syncthreads();
    {
        const int cg = tid & 31, r0 = tid >> 5;
        const float4 b4 = *reinterpret_cast<const float4*>(g_b2 + e * H2v + cg * 4);
#pragma unroll
        for (int p = 0; p < 32; ++p) {
            int r = r0 + p * 4;
            const float* s = stage + r * STG + cg * 4;
            float4 v;
            v.x = fmaxf(s[0] + b4.x, 0.0f);
            v.y = fmaxf(s[1] + b4.y, 0.0f);
            v.z = fmaxf(s[2] + b4.z, 0.0f);
            v.w = fmaxf(s[3] + b4.w, 0.0f);
            *reinterpret_cast<float4*>(g_Z + ((size_t)e * BATCH + m0 + r) * H2v + cg * 4) = v;
        }
    }
}

// ---------------- combine ----------------
__global__ void __launch_bounds__(256) combine_kernel(float* __restrict__ out) {
    const int gid = blockIdx.x * blockDim.x + threadIdx.x;
    const int b = gid >> 5, c = (gid & 31) * 4;
    if (b >= BATCH) return;
    float gw[DCv][6];
#pragma unroll
    for (int g = 0; g < DCv; ++g)
#pragma unroll
        for (int e = 0; e < 6; ++e)
            gw[g][e] = g_gates[((size_t)g * BATCH + b) * 8 + e];
    float4 acc[DCv];
#pragma unroll
    for (int g = 0; g < DCv; ++g) acc[g] = make_float4(0.f, 0.f, 0.f, 0.f);
#pragma unroll
    for (int e = 0; e < NEv; ++e) {
        float4 z = *reinterpret_cast<const float4*>(g_Z + ((size_t)e * BATCH + b) * H2v + c);
        if (e < NSv) {
#pragma unroll
            for (int g = 0; g < DCv; ++g) {
                const float w = gw[g][e];
                acc[g].x += w * z.x; acc[g].y += w * z.y;
                acc[g].z += w * z.z; acc[g].w += w * z.w;
            }
        } else {
            const int g = (e - NSv) >> 1;
            const float w = gw[g][NSv + ((e - NSv) & 1)];
            acc[g].x += w * z.x; acc[g].y += w * z.y;
            acc[g].z += w * z.z; acc[g].w += w * z.w;
        }
    }
#pragma unroll
    for (int g = 0; g < DCv; ++g)
        *reinterpret_cast<float4*>(out + ((size_t)g * BATCH + b) * H2v + c) = acc[g];
}

extern "C" void kernel_launch(void* const* d_in, const int* in_sizes, int n_in,
                              void* d_out, int out_size) {
    const float *x, *sW1, *sb1, *sW2, *sb2, *dW1, *db1, *dW2, *db2, *gW1, *gb1, *gW2, *gb2;
    if (n_in >= 14 && in_sizes[1] == BATCH) {
        x   = (const float*)d_in[0];
        sW1 = (const float*)d_in[2];  sb1 = (const float*)d_in[3];
        sW2 = (const float*)d_in[4];  sb2 = (const float*)d_in[5];
        dW1 = (const float*)d_in[6];  db1 = (const float*)d_in[7];
        dW2 = (const float*)d_in[8];  db2 = (const float*)d_in[9];
        gW1 = (const float*)d_in[10]; gb1 = (const float*)d_in[11];
        gW2 = (const float*)d_in[12]; gb2 = (const float*)d_in[13];
    } else {
        x   = (const float*)d_in[0];
        sW1 = (const float*)d_in[1];  sb1 = (const float*)d_in[2];
        sW2 = (const float*)d_in[3];  sb2 = (const float*)d_in[4];
        dW1 = (const float*)d_in[5];  db1 = (const float*)d_in[6];
        dW2 = (const float*)d_in[7];  db2 = (const float*)d_in[8];
        gW1 = (const float*)d_in[9];  gb1 = (const float*)d_in[10];
        gW2 = (const float*)d_in[11]; gb2 = (const float*)d_in[12];
    }
    float* out = (float*)d_out;

    cudaFuncSetAttribute(gemm1_kernel, cudaFuncAttributeMaxDynamicSharedMemorySize, SMEM_TOT);
    cudaFuncSetAttribute(gemm2_kernel, cudaFuncAttributeMaxDynamicSharedMemorySize, SMEM_TOT);

    cvt_x_kernel<<<(BATCH * DIMD / 4) / 256, 256>>>(x);
    pack_w1_kernel<<<dim3(NCOLS / 32, DIMD / 32), dim3(32, 8)>>>(sW1, dW1, gW1, sb1, db1, gb1);
    pack_w2_kernel<<<dim3(H2v / 32, H1v / 32, NEv), dim3(32, 8)>>>(sW2, dW2, sb2, db2);
    gemm1_kernel<<<dim3(NCOLS / 128, BATCH / 128), 128, SMEM_TOT>>>();
    gate_kernel<<<(DCv * BATCH) / 8, 256>>>(gW2, gb2);
    gemm2_kernel<<<dim3(BATCH / 128, NEv), 128, SMEM_TOT>>>();
    combine_kernel<<<(BATCH * 32) / 256, 256>>>(out);
}

// round 8
// speedup vs baseline: 1.2928x; 1.0258x over previous
#include <cuda_runtime.h>
#include <cstdint>

#define DI __device__ __forceinline__

constexpr int BATCH = 16384;
constexpr int DIMD  = 1024;
constexpr int H1v   = 256;
constexpr int H2v   = 128;
constexpr int GHv   = 64;
constexpr int NSv   = 4;
constexpr int DEv   = 2;
constexpr int DCv   = 3;
constexpr int NEv   = NSv + DCv * DEv;            // 10
constexpr int GCOL  = NEv * H1v;                  // 2560
constexpr int NCOLS = GCOL + DCv * GHv + 64;      // 2816 = 22 * 128

constexpr int KCH   = 32;
constexpr int SROW  = 36;                          // padded row stride (conflict-free)
constexpr int HBUF  = 128 * SROW * 4;              // 18432 B: one operand (128 rows x 32k)
constexpr int STAGE_B = 2 * HBUF;                  // 36864 B: A+B per stage
constexpr int NSTG  = 3;
constexpr int SMEM_TOT = NSTG * STAGE_B;           // 110592 B -> 2 CTAs/SM
constexpr int STG   = 132;

__device__ float g_X[(size_t)BATCH * DIMD];
__device__ float g_Wt1[(size_t)NCOLS * DIMD];      // [n][k] tf32
__device__ float g_b1[NCOLS];
__device__ float g_Wt2[(size_t)NEv * H2v * H1v];   // [e][o][h] tf32
__device__ float g_b2[NEv * H2v];
__device__ float g_Y[(size_t)BATCH * NCOLS];       // tf32-rounded activations
__device__ float g_Z[(size_t)NEv * BATCH * H2v];
__device__ float g_gates[(size_t)DCv * BATCH * 8];

DI uint32_t smem_u32(const void* p) {
    uint32_t a;
    asm("{ .reg .u64 t; cvta.to.shared.u64 t, %1; cvt.u32.u64 %0, t; }" : "=r"(a) : "l"(p));
    return a;
}
DI float to_tf32(float x) {
    uint32_t r;
    asm("cvt.rna.tf32.f32 %0, %1;" : "=r"(r) : "f"(x));
    return __uint_as_float(r);
}
DI void cp16(uint32_t dst, const void* src) {
    asm volatile("cp.async.cg.shared.global [%0], [%1], 16;" :: "r"(dst), "l"(src));
}
DI void cp_commit() { asm volatile("cp.async.commit_group;" ::: "memory"); }
DI void cp_wait1()  { asm volatile("cp.async.wait_group 1;" ::: "memory"); }

DI void mma8(float* d, const uint32_t* a, const uint32_t* b) {
    asm volatile("mma.sync.aligned.m16n8k8.row.col.f32.tf32.tf32.f32 "
                 "{%0,%1,%2,%3}, {%4,%5,%6,%7}, {%8,%9}, {%0,%1,%2,%3};"
                 : "+f"(d[0]), "+f"(d[1]), "+f"(d[2]), "+f"(d[3])
                 : "r"(a[0]), "r"(a[1]), "r"(a[2]), "r"(a[3]),
                   "r"(b[0]), "r"(b[1]));
}
DI void ldm4(uint32_t* r, uint32_t addr) {
    asm volatile("ldmatrix.sync.aligned.m8n8.x4.shared.b16 {%0,%1,%2,%3}, [%4];"
                 : "=r"(r[0]), "=r"(r[1]), "=r"(r[2]), "=r"(r[3]) : "r"(addr));
}

// warp tile 64x32: per ks-group 6 ldmatrix.x4 + 16 mma
DI void compute_chunk32(uint32_t aB, uint32_t bB,
                        const uint32_t* aoff, const uint32_t* boff,
                        float (&d)[4][4][4]) {
#pragma unroll
    for (int ks = 0; ks < 4; ++ks) {
        uint32_t a[4][4], b[2][4];
#pragma unroll
        for (int mt = 0; mt < 4; ++mt) ldm4(a[mt], aB + aoff[mt] + ks * 32);
#pragma unroll
        for (int p = 0; p < 2; ++p)  ldm4(b[p], bB + boff[p] + ks * 32);
#pragma unroll
        for (int mt = 0; mt < 4; ++mt)
#pragma unroll
            for (int p = 0; p < 2; ++p) {
                mma8(d[mt][2 * p],     a[mt], &b[p][0]);
                mma8(d[mt][2 * p + 1], a[mt], &b[p][2]);
            }
    }
}

// lane-constant ldmatrix byte offsets (warpM in 0..1, warpN in 0..3)
DI void make_aoff(uint32_t* aoff, int warpM, int lane) {
    const int lr = lane & 7, lq = (lane >> 3) & 1, lp = (lane >> 4) & 1;
#pragma unroll
    for (int mt = 0; mt < 4; ++mt)
        aoff[mt] = ((warpM * 64 + mt * 16 + lq * 8 + lr) * SROW + lp * 4) * 4;
}
DI void make_boff32(uint32_t* boff, int warpN, int lane) {
    const int lr = lane & 7, lq = (lane >> 3) & 1, lp = (lane >> 4) & 1;
#pragma unroll
    for (int p = 0; p < 2; ++p)
        boff[p] = ((warpN * 32 + p * 16 + lp * 8 + lr) * SROW + lq * 4) * 4;
}

// ---------------- input rounding ----------------
__global__ void cvt_x_kernel(const float* __restrict__ x) {
    const size_t i = ((size_t)blockIdx.x * blockDim.x + threadIdx.x) * 4;
    float4 v = *reinterpret_cast<const float4*>(x + i);
    v.x = to_tf32(v.x); v.y = to_tf32(v.y); v.z = to_tf32(v.z); v.w = to_tf32(v.w);
    *reinterpret_cast<float4*>(g_X + i) = v;
}

// ---------------- weight packing ----------------
DI float w1_src(int n, int d, const float* sW1, const float* dW1, const float* gW1) {
    if (n < NSv * H1v) {
        int e = n >> 8, h = n & 255;
        return sW1[((size_t)e * DIMD + d) * H1v + h];
    } else if (n < GCOL) {
        int m = n - NSv * H1v, e = m >> 8, h = m & 255;
        return dW1[((size_t)e * DIMD + d) * H1v + h];
    } else if (n < GCOL + DCv * GHv) {
        int m = n - GCOL, g = m >> 6, k = m & 63;
        return gW1[((size_t)g * DIMD + d) * GHv + k];
    }
    return 0.0f;
}

__global__ void pack_w1_kernel(const float* __restrict__ sW1, const float* __restrict__ dW1,
                               const float* __restrict__ gW1, const float* __restrict__ sb1,
                               const float* __restrict__ db1, const float* __restrict__ gb1) {
    __shared__ float t[32][33];
    const int n0 = blockIdx.x * 32, d0 = blockIdx.y * 32;
    const int tx = threadIdx.x, ty = threadIdx.y;
#pragma unroll
    for (int i = 0; i < 4; ++i)
        t[ty + i * 8][tx] = to_tf32(w1_src(n0 + tx, d0 + ty + i * 8, sW1, dW1, gW1));
    __syncthreads();
#pragma unroll
    for (int i = 0; i < 4; ++i)
        g_Wt1[(size_t)(n0 + ty + i * 8) * DIMD + d0 + tx] = t[tx][ty + i * 8];
    if (blockIdx.y == 0 && ty == 0) {
        int n = n0 + tx;
        float bv;
        if (n < NSv * H1v) bv = sb1[n];
        else if (n < GCOL) bv = db1[n - NSv * H1v];
        else if (n < GCOL + DCv * GHv) bv = gb1[n - GCOL];
        else bv = 0.0f;
        g_b1[n] = bv;
    }
}

__global__ void pack_w2_kernel(const float* __restrict__ sW2, const float* __restrict__ dW2,
                               const float* __restrict__ sb2, const float* __restrict__ db2) {
    __shared__ float t[32][33];
    const int o0 = blockIdx.x * 32, h0 = blockIdx.y * 32, e = blockIdx.z;
    const int tx = threadIdx.x, ty = threadIdx.y;
#pragma unroll
    for (int i = 0; i < 4; ++i) {
        int h = h0 + ty + i * 8, o = o0 + tx;
        float v = (e < NSv) ? sW2[((size_t)e * H1v + h) * H2v + o]
                            : dW2[((size_t)(e - NSv) * H1v + h) * H2v + o];
        t[ty + i * 8][tx] = to_tf32(v);
    }
    __syncthreads();
#pragma unroll
    for (int i = 0; i < 4; ++i) {
        int o = o0 + ty + i * 8, h = h0 + tx;
        g_Wt2[((size_t)e * H2v + o) * H1v + h] = t[tx][ty + i * 8];
    }
    if (blockIdx.y == 0 && ty == 0) {
        int o = o0 + tx;
        g_b2[e * H2v + o] = (e < NSv) ? sb2[e * H2v + o] : db2[(e - NSv) * H2v + o];
    }
}

// ---------------- GEMM1: Y = tf32(relu(X @ W1cat + b1)), 256 thr, 8 warps 64x32, 3-stage ----------------
__global__ void __launch_bounds__(256, 2) gemm1_kernel() {
    extern __shared__ char smem[];
    const uint32_t sbase = smem_u32(smem);
    const int tid = threadIdx.x, wid = tid >> 5, lane = tid & 31;
    const int warpM = wid >> 2, warpN = wid & 3;   // 2 M x 4 N of 64x32
    const int g = lane >> 2, tg = lane & 3;
    const int n0 = blockIdx.x * 128, m0 = blockIdx.y * 128;   // N fastest -> X L2-hot

    uint32_t aoff[4], boff[2];
    make_aoff(aoff, warpM, lane);
    make_boff32(boff, warpN, lane);

    float d[4][4][4] = {};

    auto load = [&](int stg, int ck) {
        const float* xa = g_X + (size_t)m0 * DIMD + ck * KCH;
        const float* wb = g_Wt1 + (size_t)n0 * DIMD + ck * KCH;
        const uint32_t da = sbase + stg * STAGE_B;
        const uint32_t db = da + HBUF;
#pragma unroll
        for (int it = 0; it < 4; ++it) {
            int idx = tid + it * 256, r = idx >> 3, cc = idx & 7;
            cp16(da + r * 144 + cc * 16, xa + (size_t)r * DIMD + cc * 4);
            cp16(db + r * 144 + cc * 16, wb + (size_t)r * DIMD + cc * 4);
        }
        cp_commit();
    };

    load(0, 0);
    load(1, 1);
    for (int ck = 0; ck < 32; ++ck) {
        cp_wait1();
        __syncthreads();
        if (ck + 2 < 32) load((ck + 2) % NSTG, ck + 2);
        else cp_commit();                       // empty group keeps wait counts uniform
        const uint32_t aB = sbase + (ck % NSTG) * STAGE_B;
        compute_chunk32(aB, aB + HBUF, aoff, boff, d);
    }
    __syncthreads();

    float* stage = reinterpret_cast<float*>(smem);
#pragma unroll
    for (int mt = 0; mt < 4; ++mt)
#pragma unroll
        for (int nt = 0; nt < 4; ++nt)
#pragma unroll
            for (int i = 0; i < 4; ++i) {
                int r = warpM * 64 + mt * 16 + g + ((i >= 2) ? 8 : 0);
                int cc = warpN * 32 + nt * 8 + tg * 2 + (i & 1);
                stage[r * STG + cc] = d[mt][nt][i];
            }
    __syncthreads();
    {
        const int cg = tid & 31, r0 = tid >> 5;
        const float4 b4 = *reinterpret_cast<const float4*>(g_b1 + n0 + cg * 4);
#pragma unroll
        for (int p = 0; p < 16; ++p) {
            int r = r0 + p * 8;
            const float* s = stage + r * STG + cg * 4;
            float4 v;
            v.x = to_tf32(fmaxf(s[0] + b4.x, 0.0f));
            v.y = to_tf32(fmaxf(s[1] + b4.y, 0.0f));
            v.z = to_tf32(fmaxf(s[2] + b4.z, 0.0f));
            v.w = to_tf32(fmaxf(s[3] + b4.w, 0.0f));
            *reinterpret_cast<float4*>(g_Y + (size_t)(m0 + r) * NCOLS + n0 + cg * 4) = v;
        }
    }
}

// ---------------- gates ----------------
__global__ void __launch_bounds__(256) gate_kernel(const float* __restrict__ gW2,
                                                   const float* __restrict__ gb2) {
    const int gw = (blockIdx.x * blockDim.x + threadIdx.x) >> 5;
    const int lane = threadIdx.x & 31;
    if (gw >= DCv * BATCH) return;
    const int g = gw / BATCH, b = gw % BATCH;
    const float* yr = g_Y + (size_t)b * NCOLS + GCOL + g * GHv;
    const float h0 = yr[2 * lane], h1 = yr[2 * lane + 1];
    const float* w = gW2 + (size_t)g * GHv * 6;
    float acc[6];
#pragma unroll
    for (int e = 0; e < 6; ++e)
        acc[e] = h0 * w[(2 * lane) * 6 + e] + h1 * w[(2 * lane + 1) * 6 + e];
#pragma unroll
    for (int e = 0; e < 6; ++e)
#pragma unroll
        for (int s = 16; s; s >>= 1) acc[e] += __shfl_xor_sync(0xFFFFFFFFu, acc[e], s);
    if (lane == 0) {
        float m = -1e30f;
#pragma unroll
        for (int e = 0; e < 6; ++e) { acc[e] += gb2[g * 6 + e]; m = fmaxf(m, acc[e]); }
        float s = 0.0f;
#pragma unroll
        for (int e = 0; e < 6; ++e) { acc[e] = expf(acc[e] - m); s += acc[e]; }
        const float inv = 1.0f / s;
#pragma unroll
        for (int e = 0; e < 6; ++e)
            g_gates[((size_t)g * BATCH + b) * 8 + e] = acc[e] * inv;
    }
}

// ---------------- GEMM2: Z[e] = relu(Y_e @ W2_e + b2_e), grid (m, e), 3-stage ----------------
__global__ void __launch_bounds__(256, 2) gemm2_kernel() {
    extern __shared__ char smem[];
    const uint32_t sbase = smem_u32(smem);
    const int tid = threadIdx.x, wid = tid >> 5, lane = tid & 31;
    const int warpM = wid >> 2, warpN = wid & 3;   // 2 M x 4 N of 64x32
    const int g = lane >> 2, tg = lane & 3;
    const int m0 = blockIdx.x * 128, e = blockIdx.y;

    uint32_t aoff[4], boff[2];
    make_aoff(aoff, warpM, lane);
    make_boff32(boff, warpN, lane);

    float d[4][4][4] = {};

    auto load = [&](int stg, int ck) {
        const float* ya = g_Y + (size_t)m0 * NCOLS + e * H1v + ck * KCH;
        const float* wb = g_Wt2 + (size_t)e * H2v * H1v + ck * KCH;
        const uint32_t da = sbase + stg * STAGE_B;
        const uint32_t db = da + HBUF;
#pragma unroll
        for (int it = 0; it < 4; ++it) {
            int ii = tid + it * 256, r = ii >> 3, cc = ii & 7;
            cp16(da + r * 144 + cc * 16, ya + (size_t)r * NCOLS + cc * 4);
            cp16(db + r * 144 + cc * 16, wb + (size_t)r * H1v + cc * 4);
        }
        cp_commit();
    };

    load(0, 0);
    load(1, 1);
    for (int ck = 0; ck < 8; ++ck) {
        cp_wait1();
        __syncthreads();
        if (ck + 2 < 8) load((ck + 2) % NSTG, ck + 2);
        else cp_commit();
        const uint32_t aB = sbase + (ck % NSTG) * STAGE_B;
        compute_chunk32(aB, aB + HBUF, aoff, boff, d);
    }
    __syncthreads();

    float* stage = reinterpret_cast<float*>(smem);
#pragma unroll
    for (int mt = 0; mt < 4; ++mt)
#pragma unroll
        for (int nt = 0; nt < 4; ++nt)
#pragma unroll
            for (int i = 0; i < 4; ++i) {
                int r = warpM * 64 + mt * 16 + g + ((i >= 2) ? 8 : 0);
                int cc = warpN * 32 + nt * 8 + tg * 2 + (i & 1);
                stage[r * STG + cc] = d[mt][nt][i];
            }
    __syncthreads();
    {
        const int cg = tid & 31, r0 = tid >> 5;
        const float4 b4 = *reinterpret_cast<const float4*>(g_b2 + e * H2v + cg * 4);
#pragma unroll
        for (int p = 0; p < 16; ++p) {
            int r = r0 + p * 8;
            const float* s = stage + r * STG + cg * 4;
            float4 v;
            v.x = fmaxf(s[0] + b4.x, 0.0f);
            v.y = fmaxf(s[1] + b4.y, 0.0f);
            v.z = fmaxf(s[2] + b4.z, 0.0f);
            v.w = fmaxf(s[3] + b4.w, 0.0f);
            *reinterpret_cast<float4*>(g_Z + ((size_t)e * BATCH + m0 + r) * H2v + cg * 4) = v;
        }
    }
}

// ---------------- combine ----------------
__global__ void __launch_bounds__(256) combine_kernel(float* __restrict__ out) {
    const int gid = blockIdx.x * blockDim.x + threadIdx.x;
    const int b = gid >> 5, c = (gid & 31) * 4;
    if (b >= BATCH) return;
    float gw[DCv][6];
#pragma unroll
    for (int g = 0; g < DCv; ++g)
#pragma unroll
        for (int e = 0; e < 6; ++e)
            gw[g][e] = g_gates[((size_t)g * BATCH + b) * 8 + e];
    float4 acc[DCv];
#pragma unroll
    for (int g = 0; g < DCv; ++g) acc[g] = make_float4(0.f, 0.f, 0.f, 0.f);
#pragma unroll
    for (int e = 0; e < NEv; ++e) {
        float4 z = *reinterpret_cast<const float4*>(g_Z + ((size_t)e * BATCH + b) * H2v + c);
        if (e < NSv) {
#pragma unroll
            for (int g = 0; g < DCv; ++g) {
                const float w = gw[g][e];
                acc[g].x += w * z.x; acc[g].y += w * z.y;
                acc[g].z += w * z.z; acc[g].w += w * z.w;
            }
        } else {
            const int g = (e - NSv) >> 1;
            const float w = gw[g][NSv + ((e - NSv) & 1)];
            acc[g].x += w * z.x; acc[g].y += w * z.y;
            acc[g].z += w * z.z; acc[g].w += w * z.w;
        }
    }
#pragma unroll
    for (int g = 0; g < DCv; ++g)
        *reinterpret_cast<float4*>(out + ((size_t)g * BATCH + b) * H2v + c) = acc[g];
}

extern "C" void kernel_launch(void* const* d_in, const int* in_sizes, int n_in,
                              void* d_out, int out_size) {
    const float *x, *sW1, *sb1, *sW2, *sb2, *dW1, *db1, *dW2, *db2, *gW1, *gb1, *gW2, *gb2;
    if (n_in >= 14 && in_sizes[1] == BATCH) {
        x   = (const float*)d_in[0];
        sW1 = (const float*)d_in[2];  sb1 = (const float*)d_in[3];
        sW2 = (const float*)d_in[4];  sb2 = (const float*)d_in[5];
        dW1 = (const float*)d_in[6];  db1 = (const float*)d_in[7];
        dW2 = (const float*)d_in[8];  db2 = (const float*)d_in[9];
        gW1 = (const float*)d_in[10]; gb1 = (const float*)d_in[11];
        gW2 = (const float*)d_in[12]; gb2 = (const float*)d_in[13];
    } else {
        x   = (const float*)d_in[0];
        sW1 = (const float*)d_in[1];  sb1 = (const float*)d_in[2];
        sW2 = (const float*)d_in[3];  sb2 = (const float*)d_in[4];
        dW1 = (const float*)d_in[5];  db1 = (const float*)d_in[6];
        dW2 = (const float*)d_in[7];  db2 = (const float*)d_in[8];
        gW1 = (const float*)d_in[9];  gb1 = (const float*)d_in[10];
        gW2 = (const float*)d_in[11]; gb2 = (const float*)d_in[12];
    }
    float* out = (float*)d_out;

    cudaFuncSetAttribute(gemm1_kernel, cudaFuncAttributeMaxDynamicSharedMemorySize, SMEM_TOT);
    cudaFuncSetAttribute(gemm2_kernel, cudaFuncAttributeMaxDynamicSharedMemorySize, SMEM_TOT);

    cvt_x_kernel<<<(BATCH * DIMD / 4) / 256, 256>>>(x);
    pack_w1_kernel<<<dim3(NCOLS / 32, DIMD / 32), dim3(32, 8)>>>(sW1, dW1, gW1, sb1, db1, gb1);
    pack_w2_kernel<<<dim3(H2v / 32, H1v / 32, NEv), dim3(32, 8)>>>(sW2, dW2, sb2, db2);
    gemm1_kernel<<<dim3(NCOLS / 128, BATCH / 128), 256, SMEM_TOT>>>();
    gate_kernel<<<(DCv * BATCH) / 8, 256>>>(gW2, gb2);
    gemm2_kernel<<<dim3(BATCH / 128, NEv), 256, SMEM_TOT>>>();
    combine_kernel<<<(BATCH * 32) / 256, 256>>>(out);
}

// round 11
// speedup vs baseline: 2.0155x; 1.5591x over previous
#include <cuda_runtime.h>
#include <cuda_fp16.h>
#include <cstdint>

#define DI __device__ __forceinline__

constexpr int BATCH = 16384;
constexpr int DIMD  = 1024;
constexpr int H1v   = 256;
constexpr int H2v   = 128;
constexpr int GHv   = 64;
constexpr int NSv   = 4;
constexpr int DEv   = 2;
constexpr int DCv   = 3;
constexpr int NEv   = NSv + DCv * DEv;            // 10
constexpr int GCOL  = NEv * H1v;                  // 2560
constexpr int NCOLS = GCOL + DCv * GHv + 64;      // 2816 = 22 * 128

constexpr int KCH   = 32;                          // halves per chunk
constexpr int SROW  = 40;                          // halves per smem row (80 B, conflict-free)
constexpr int HBUF  = 128 * SROW * 2;              // 10240 B per operand
constexpr int STAGE_B = 2 * HBUF;                  // 20480 B per stage
constexpr int NSTG  = 3;
constexpr int STG   = 132;                         // fp32 epilogue stage stride
constexpr int SMEM_TOT = 128 * STG * 4;            // 67584 B (> 3*STAGE_B = 61440)

__device__ __half g_X[(size_t)BATCH * DIMD];
__device__ __half g_Wt1[(size_t)NCOLS * DIMD];     // [n][k] fp16
__device__ float  g_b1[NCOLS];
__device__ __half g_Wt2[(size_t)NEv * H2v * H1v];  // [e][o][h] fp16
__device__ float  g_b2[NEv * H2v];
__device__ __half g_Y[(size_t)BATCH * NCOLS];      // fp16 activations
__device__ float  g_Z[(size_t)NEv * BATCH * H2v];
__device__ float  g_gates[(size_t)DCv * BATCH * 8];

DI uint32_t smem_u32(const void* p) {
    uint32_t a;
    asm("{ .reg .u64 t; cvta.to.shared.u64 t, %1; cvt.u32.u64 %0, t; }" : "=r"(a) : "l"(p));
    return a;
}
DI void cp16(uint32_t dst, const void* src) {
    asm volatile("cp.async.cg.shared.global [%0], [%1], 16;" :: "r"(dst), "l"(src));
}
DI void cp_commit() { asm volatile("cp.async.commit_group;" ::: "memory"); }
DI void cp_wait1()  { asm volatile("cp.async.wait_group 1;" ::: "memory"); }

DI void mma16(float* d, const uint32_t* a, const uint32_t* b) {
    asm volatile("mma.sync.aligned.m16n8k16.row.col.f32.f16.f16.f32 "
                 "{%0,%1,%2,%3}, {%4,%5,%6,%7}, {%8,%9}, {%0,%1,%2,%3};"
                 : "+f"(d[0]), "+f"(d[1]), "+f"(d[2]), "+f"(d[3])
                 : "r"(a[0]), "r"(a[1]), "r"(a[2]), "r"(a[3]),
                   "r"(b[0]), "r"(b[1]));
}
DI void ldm4(uint32_t* r, uint32_t addr) {
    asm volatile("ldmatrix.sync.aligned.m8n8.x4.shared.b16 {%0,%1,%2,%3}, [%4];"
                 : "=r"(r[0]), "=r"(r[1]), "=r"(r[2]), "=r"(r[3]) : "r"(addr));
}

// warp tile 64x32, k-chunk 32 = 2 k-steps of m16n8k16: per ks 6 ldmatrix.x4 + 16 mma
DI void compute_chunk16(uint32_t aB, uint32_t bB,
                        const uint32_t* aoff, const uint32_t* boff,
                        float (&d)[4][4][4]) {
#pragma unroll
    for (int ks = 0; ks < 2; ++ks) {
        uint32_t a[4][4], b[2][4];
#pragma unroll
        for (int mt = 0; mt < 4; ++mt) ldm4(a[mt], aB + aoff[mt] + ks * 32);
#pragma unroll
        for (int p = 0; p < 2; ++p)  ldm4(b[p], bB + boff[p] + ks * 32);
#pragma unroll
        for (int mt = 0; mt < 4; ++mt)
#pragma unroll
            for (int p = 0; p < 2; ++p) {
                mma16(d[mt][2 * p],     a[mt], &b[p][0]);
                mma16(d[mt][2 * p + 1], a[mt], &b[p][2]);
            }
    }
}

// A: 16x16 tile per mt. lanes 0-15 -> rows, k-half 0; lanes 16-31 -> rows, k-half 1.
DI void make_aoff(uint32_t* aoff, int warpM, int lane) {
    const int lr = lane & 15, lk = (lane >> 4) & 1;
#pragma unroll
    for (int mt = 0; mt < 4; ++mt)
        aoff[mt] = ((warpM * 64 + mt * 16 + lr) * SROW + lk * 8) * 2;
}
// B: 16(n)x16(k) tile per p. lanes: b3 = k-half, b4 = n-half.
DI void make_boff(uint32_t* boff, int warpN, int lane) {
    const int lr = lane & 7, lk = (lane >> 3) & 1, ln = (lane >> 4) & 1;
#pragma unroll
    for (int p = 0; p < 2; ++p)
        boff[p] = ((warpN * 32 + p * 16 + ln * 8 + lr) * SROW + lk * 8) * 2;
}

// ---------------- input conversion ----------------
__global__ void cvt_x_kernel(const float* __restrict__ x) {
    const size_t i = ((size_t)blockIdx.x * blockDim.x + threadIdx.x) * 4;
    float4 v = *reinterpret_cast<const float4*>(x + i);
    __half2 h01 = __floats2half2_rn(v.x, v.y);
    __half2 h23 = __floats2half2_rn(v.z, v.w);
    uint2 u;
    u.x = *reinterpret_cast<uint32_t*>(&h01);
    u.y = *reinterpret_cast<uint32_t*>(&h23);
    *reinterpret_cast<uint2*>(g_X + i) = u;
}

// ---------------- weight packing ----------------
DI float w1_src(int n, int d, const float* sW1, const float* dW1, const float* gW1) {
    if (n < NSv * H1v) {
        int e = n >> 8, h = n & 255;
        return sW1[((size_t)e * DIMD + d) * H1v + h];
    } else if (n < GCOL) {
        int m = n - NSv * H1v, e = m >> 8, h = m & 255;
        return dW1[((size_t)e * DIMD + d) * H1v + h];
    } else if (n < GCOL + DCv * GHv) {
        int m = n - GCOL, g = m >> 6, k = m & 63;
        return gW1[((size_t)g * DIMD + d) * GHv + k];
    }
    return 0.0f;
}

__global__ void pack_w1_kernel(const float* __restrict__ sW1, const float* __restrict__ dW1,
                               const float* __restrict__ gW1, const float* __restrict__ sb1,
                               const float* __restrict__ db1, const float* __restrict__ gb1) {
    __shared__ float t[32][33];
    const int n0 = blockIdx.x * 32, d0 = blockIdx.y * 32;
    const int tx = threadIdx.x, ty = threadIdx.y;
#pragma unroll
    for (int i = 0; i < 4; ++i)
        t[ty + i * 8][tx] = w1_src(n0 + tx, d0 + ty + i * 8, sW1, dW1, gW1);
    __syncthreads();
#pragma unroll
    for (int i = 0; i < 4; ++i)
        g_Wt1[(size_t)(n0 + ty + i * 8) * DIMD + d0 + tx] = __float2half_rn(t[tx][ty + i * 8]);
    if (blockIdx.y == 0 && ty == 0) {
        int n = n0 + tx;
        float bv;
        if (n < NSv * H1v) bv = sb1[n];
        else if (n < GCOL) bv = db1[n - NSv * H1v];
        else if (n < GCOL + DCv * GHv) bv = gb1[n - GCOL];
        else bv = 0.0f;
        g_b1[n] = bv;
    }
}

__global__ void pack_w2_kernel(const float* __restrict__ sW2, const float* __restrict__ dW2,
                               const float* __restrict__ sb2, const float* __restrict__ db2) {
    __shared__ float t[32][33];
    const int o0 = blockIdx.x * 32, h0 = blockIdx.y * 32, e = blockIdx.z;
    const int tx = threadIdx.x, ty = threadIdx.y;
#pragma unroll
    for (int i = 0; i < 4; ++i) {
        int h = h0 + ty + i * 8, o = o0 + tx;
        float v = (e < NSv) ? sW2[((size_t)e * H1v + h) * H2v + o]
                            : dW2[((size_t)(e - NSv) * H1v + h) * H2v + o];
        t[ty + i * 8][tx] = v;
    }
    __syncthreads();
#pragma unroll
    for (int i = 0; i < 4; ++i) {
        int o = o0 + ty + i * 8, h = h0 + tx;
        g_Wt2[((size_t)e * H2v + o) * H1v + h] = __float2half_rn(t[tx][ty + i * 8]);
    }
    if (blockIdx.y == 0 && ty == 0) {
        int o = o0 + tx;
        g_b2[e * H2v + o] = (e < NSv) ? sb2[e * H2v + o] : db2[(e - NSv) * H2v + o];
    }
}

// ---------------- GEMM1: Y = fp16(relu(X @ W1cat + b1)), 256 thr, 8 warps 64x32, 3-stage ----------------
__global__ void __launch_bounds__(256, 2) gemm1_kernel() {
    extern __shared__ char smem[];
    const uint32_t sbase = smem_u32(smem);
    const int tid = threadIdx.x, wid = tid >> 5, lane = tid & 31;
    const int warpM = wid >> 2, warpN = wid & 3;   // 2 M x 4 N of 64x32
    const int g = lane >> 2, tg = lane & 3;
    const int n0 = blockIdx.x * 128, m0 = blockIdx.y * 128;   // N fastest -> X L2-hot

    uint32_t aoff[4], boff[2];
    make_aoff(aoff, warpM, lane);
    make_boff(boff, warpN, lane);

    float d[4][4][4] = {};

    auto load = [&](int stg, int ck) {
        const __half* xa = g_X + (size_t)m0 * DIMD + ck * KCH;
        const __half* wb = g_Wt1 + (size_t)n0 * DIMD + ck * KCH;
        const uint32_t da = sbase + stg * STAGE_B;
        const uint32_t db = da + HBUF;
#pragma unroll
        for (int it = 0; it < 2; ++it) {
            int idx = tid + it * 256, r = idx >> 2, cc = idx & 3;
            cp16(da + r * 80 + cc * 16, xa + (size_t)r * DIMD + cc * 8);
            cp16(db + r * 80 + cc * 16, wb + (size_t)r * DIMD + cc * 8);
        }
        cp_commit();
    };

    load(0, 0);
    load(1, 1);
    for (int ck = 0; ck < 32; ++ck) {
        cp_wait1();
        __syncthreads();
        if (ck + 2 < 32) load((ck + 2) % NSTG, ck + 2);
        else cp_commit();
        const uint32_t aB = sbase + (ck % NSTG) * STAGE_B;
        compute_chunk16(aB, aB + HBUF, aoff, boff, d);
    }
    __syncthreads();

    float* stage = reinterpret_cast<float*>(smem);
#pragma unroll
    for (int mt = 0; mt < 4; ++mt)
#pragma unroll
        for (int nt = 0; nt < 4; ++nt)
#pragma unroll
            for (int i = 0; i < 4; ++i) {
                int r = warpM * 64 + mt * 16 + g + ((i >= 2) ? 8 : 0);
                int cc = warpN * 32 + nt * 8 + tg * 2 + (i & 1);
                stage[r * STG + cc] = d[mt][nt][i];
            }
    __syncthreads();
    {
        const int cg = tid & 31, r0 = tid >> 5;
        const float4 b4 = *reinterpret_cast<const float4*>(g_b1 + n0 + cg * 4);
#pragma unroll
        for (int p = 0; p < 16; ++p) {
            int r = r0 + p * 8;
            const float* s = stage + r * STG + cg * 4;
            __half2 h01 = __floats2half2_rn(fmaxf(s[0] + b4.x, 0.0f), fmaxf(s[1] + b4.y, 0.0f));
            __half2 h23 = __floats2half2_rn(fmaxf(s[2] + b4.z, 0.0f), fmaxf(s[3] + b4.w, 0.0f));
            uint2 u;
            u.x = *reinterpret_cast<uint32_t*>(&h01);
            u.y = *reinterpret_cast<uint32_t*>(&h23);
            *reinterpret_cast<uint2*>(g_Y + (size_t)(m0 + r) * NCOLS + n0 + cg * 4) = u;
        }
    }
}

// ---------------- gates ----------------
__global__ void __launch_bounds__(256) gate_kernel(const float* __restrict__ gW2,
                                                   const float* __restrict__ gb2) {
    const int gw = (blockIdx.x * blockDim.x + threadIdx.x) >> 5;
    const int lane = threadIdx.x & 31;
    if (gw >= DCv * BATCH) return;
    const int g = gw / BATCH, b = gw % BATCH;
    const __half* yr = g_Y + (size_t)b * NCOLS + GCOL + g * GHv;
    const float h0 = __half2float(yr[2 * lane]), h1 = __half2float(yr[2 * lane + 1]);
    const float* w = gW2 + (size_t)g * GHv * 6;
    float acc[6];
#pragma unroll
    for (int e = 0; e < 6; ++e)
        acc[e] = h0 * w[(2 * lane) * 6 + e] + h1 * w[(2 * lane + 1) * 6 + e];
#pragma unroll
    for (int e = 0; e < 6; ++e)
#pragma unroll
        for (int s = 16; s; s >>= 1) acc[e] += __shfl_xor_sync(0xFFFFFFFFu, acc[e], s);
    if (lane == 0) {
        float m = -1e30f;
#pragma unroll
        for (int e = 0; e < 6; ++e) { acc[e] += gb2[g * 6 + e]; m = fmaxf(m, acc[e]); }
        float s = 0.0f;
#pragma unroll
        for (int e = 0; e < 6; ++e) { acc[e] = expf(acc[e] - m); s += acc[e]; }
        const float inv = 1.0f / s;
#pragma unroll
        for (int e = 0; e < 6; ++e)
            g_gates[((size_t)g * BATCH + b) * 8 + e] = acc[e] * inv;
    }
}

// ---------------- GEMM2: Z[e] = relu(Y_e @ W2_e + b2_e), grid (m, e), 3-stage ----------------
__global__ void __launch_bounds__(256, 2) gemm2_kernel() {
    extern __shared__ char smem[];
    const uint32_t sbase = smem_u32(smem);
    const int tid = threadIdx.x, wid = tid >> 5, lane = tid & 31;
    const int warpM = wid >> 2, warpN = wid & 3;
    const int g = lane >> 2, tg = lane & 3;
    const int m0 = blockIdx.x * 128, e = blockIdx.y;

    uint32_t aoff[4], boff[2];
    make_aoff(aoff, warpM, lane);
    make_boff(boff, warpN, lane);

    float d[4][4][4] = {};

    auto load = [&](int stg, int ck) {
        const __half* ya = g_Y + (size_t)m0 * NCOLS + e * H1v + ck * KCH;
        const __half* wb = g_Wt2 + (size_t)e * H2v * H1v + ck * KCH;
        const uint32_t da = sbase + stg * STAGE_B;
        const uint32_t db = da + HBUF;
#pragma unroll
        for (int it = 0; it < 2; ++it) {
            int ii = tid + it * 256, r = ii >> 2, cc = ii & 3;
            cp16(da + r * 80 + cc * 16, ya + (size_t)r * NCOLS + cc * 8);
            cp16(db + r * 80 + cc * 16, wb + (size_t)r * H1v + cc * 8);
        }
        cp_commit();
    };

    load(0, 0);
    load(1, 1);
    for (int ck = 0; ck < 8; ++ck) {
        cp_wait1();
        __syncthreads();
        if (ck + 2 < 8) load((ck + 2) % NSTG, ck + 2);
        else cp_commit();
        const uint32_t aB = sbase + (ck % NSTG) * STAGE_B;
        compute_chunk16(aB, aB + HBUF, aoff, boff, d);
    }
    __syncthreads();

    float* stage = reinterpret_cast<float*>(smem);
#pragma unroll
    for (int mt = 0; mt < 4; ++mt)
#pragma unroll
        for (int nt = 0; nt < 4; ++nt)
#pragma unroll
            for (int i = 0; i < 4; ++i) {
                int r = warpM * 64 + mt * 16 + g + ((i >= 2) ? 8 : 0);
                int cc = warpN * 32 + nt * 8 + tg * 2 + (i & 1);
                stage[r * STG + cc] = d[mt][nt][i];
            }
    __syncthreads();
    {
        const int cg = tid & 31, r0 = tid >> 5;
        const float4 b4 = *reinterpret_cast<const float4*>(g_b2 + e * H2v + cg * 4);
#pragma unroll
        for (int p = 0; p < 16; ++p) {
            int r = r0 + p * 8;
            const float* s = stage + r * STG + cg * 4;
            float4 v;
            v.x = fmaxf(s[0] + b4.x, 0.0f);
            v.y = fmaxf(s[1] + b4.y, 0.0f);
            v.z = fmaxf(s[2] + b4.z, 0.0f);
            v.w = fmaxf(s[3] + b4.w, 0.0f);
            *reinterpret_cast<float4*>(g_Z + ((size_t)e * BATCH + m0 + r) * H2v + cg * 4) = v;
        }
    }
}

// ---------------- combine ----------------
__global__ void __launch_bounds__(256) combine_kernel(float* __restrict__ out) {
    const int gid = blockIdx.x * blockDim.x + threadIdx.x;
    const int b = gid >> 5, c = (gid & 31) * 4;
    if (b >= BATCH) return;
    float gw[DCv][6];
#pragma unroll
    for (int g = 0; g < DCv; ++g)
#pragma unroll
        for (int e = 0; e < 6; ++e)
            gw[g][e] = g_gates[((size_t)g * BATCH + b) * 8 + e];
    float4 acc[DCv];
#pragma unroll
    for (int g = 0; g < DCv; ++g) acc[g] = make_float4(0.f, 0.f, 0.f, 0.f);
#pragma unroll
    for (int e = 0; e < NEv; ++e) {
        float4 z = *reinterpret_cast<const float4*>(g_Z + ((size_t)e * BATCH + b) * H2v + c);
        if (e < NSv) {
#pragma unroll
            for (int g = 0; g < DCv; ++g) {
                const float w = gw[g][e];
                acc[g].x += w * z.x; acc[g].y += w * z.y;
                acc[g].z += w * z.z; acc[g].w += w * z.w;
            }
        } else {
            const int g = (e - NSv) >> 1;
            const float w = gw[g][NSv + ((e - NSv) & 1)];
            acc[g].x += w * z.x; acc[g].y += w * z.y;
            acc[g].z += w * z.z; acc[g].w += w * z.w;
        }
    }
#pragma unroll
    for (int g = 0; g < DCv; ++g)
        *reinterpret_cast<float4*>(out + ((size_t)g * BATCH + b) * H2v + c) = acc[g];
}

extern "C" void kernel_launch(void* const* d_in, const int* in_sizes, int n_in,
                              void* d_out, int out_size) {
    const float *x, *sW1, *sb1, *sW2, *sb2, *dW1, *db1, *dW2, *db2, *gW1, *gb1, *gW2, *gb2;
    if (n_in >= 14 && in_sizes[1] == BATCH) {
        x   = (const float*)d_in[0];
        sW1 = (const float*)d_in[2];  sb1 = (const float*)d_in[3];
        sW2 = (const float*)d_in[4];  sb2 = (const float*)d_in[5];
        dW1 = (const float*)d_in[6];  db1 = (const float*)d_in[7];
        dW2 = (const float*)d_in[8];  db2 = (const float*)d_in[9];
        gW1 = (const float*)d_in[10]; gb1 = (const float*)d_in[11];
        gW2 = (const float*)d_in[12]; gb2 = (const float*)d_in[13];
    } else {
        x   = (const float*)d_in[0];
        sW1 = (const float*)d_in[1];  sb1 = (const float*)d_in[2];
        sW2 = (const float*)d_in[3];  sb2 = (const float*)d_in[4];
        dW1 = (const float*)d_in[5];  db1 = (const float*)d_in[6];
        dW2 = (const float*)d_in[7];  db2 = (const float*)d_in[8];
        gW1 = (const float*)d_in[9];  gb1 = (const float*)d_in[10];
        gW2 = (const float*)d_in[11]; gb2 = (const float*)d_in[12];
    }
    float* out = (float*)d_out;

    cudaFuncSetAttribute(gemm1_kernel, cudaFuncAttributeMaxDynamicSharedMemorySize, SMEM_TOT);
    cudaFuncSetAttribute(gemm2_kernel, cudaFuncAttributeMaxDynamicSharedMemorySize, SMEM_TOT);

    cvt_x_kernel<<<(BATCH * DIMD / 4) / 256, 256>>>(x);
    pack_w1_kernel<<<dim3(NCOLS / 32, DIMD / 32), dim3(32, 8)>>>(sW1, dW1, gW1, sb1, db1, gb1);
    pack_w2_kernel<<<dim3(H2v / 32, H1v / 32, NEv), dim3(32, 8)>>>(sW2, dW2, sb2, db2);
    gemm1_kernel<<<dim3(NCOLS / 128, BATCH / 128), 256, SMEM_TOT>>>();
    gate_kernel<<<(DCv * BATCH) / 8, 256>>>(gW2, gb2);
    gemm2_kernel<<<dim3(BATCH / 128, NEv), 256, SMEM_TOT>>>();
    combine_kernel<<<(BATCH * 32) / 256, 256>>>(out);
}

// round 12
// speedup vs baseline: 2.2403x; 1.1115x over previous
#include <cuda_runtime.h>
#include <cuda_fp16.h>
#include <cstdint>

#define DI __device__ __forceinline__

constexpr int BATCH = 16384;
constexpr int DIMD  = 1024;
constexpr int H1v   = 256;
constexpr int H2v   = 128;
constexpr int GHv   = 64;
constexpr int NSv   = 4;
constexpr int DEv   = 2;
constexpr int DCv   = 3;
constexpr int NEv   = NSv + DCv * DEv;            // 10
constexpr int GCOL  = NEv * H1v;                  // 2560
constexpr int NCOLS = GCOL + DCv * GHv + 64;      // 2816 = 22 * 128

constexpr int KCH   = 64;                          // halves per chunk
constexpr int KS    = KCH / 16;                    // 4 k-steps per chunk
constexpr int SROW  = 72;                          // halves per smem row (144 B, conflict-free)
constexpr int HBUF  = 128 * SROW * 2;              // 18432 B per operand
constexpr int STAGE_B = 2 * HBUF;                  // 36864 B per stage
constexpr int NSTG  = 3;
constexpr int STG   = 132;                         // fp32 epilogue stage stride
constexpr int SMEM_TOT = NSTG * STAGE_B;           // 110592 B -> 2 CTAs/SM

__device__ __half g_X[(size_t)BATCH * DIMD];
__device__ __half g_Wt1[(size_t)NCOLS * DIMD];     // [n][k] fp16
__device__ float  g_b1[NCOLS];
__device__ __half g_Wt2[(size_t)NEv * H2v * H1v];  // [e][o][h] fp16
__device__ float  g_b2[NEv * H2v];
__device__ __half g_Y[(size_t)BATCH * NCOLS];      // fp16 activations
__device__ float  g_Z[(size_t)NEv * BATCH * H2v];
__device__ float  g_gates[(size_t)DCv * BATCH * 8];

DI uint32_t smem_u32(const void* p) {
    uint32_t a;
    asm("{ .reg .u64 t; cvta.to.shared.u64 t, %1; cvt.u32.u64 %0, t; }" : "=r"(a) : "l"(p));
    return a;
}
DI void cp16(uint32_t dst, const void* src) {
    asm volatile("cp.async.cg.shared.global [%0], [%1], 16;" :: "r"(dst), "l"(src));
}
DI void cp_commit() { asm volatile("cp.async.commit_group;" ::: "memory"); }
DI void cp_wait1()  { asm volatile("cp.async.wait_group 1;" ::: "memory"); }

DI void mma16(float* d, const uint32_t* a, const uint32_t* b) {
    asm volatile("mma.sync.aligned.m16n8k16.row.col.f32.f16.f16.f32 "
                 "{%0,%1,%2,%3}, {%4,%5,%6,%7}, {%8,%9}, {%0,%1,%2,%3};"
                 : "+f"(d[0]), "+f"(d[1]), "+f"(d[2]), "+f"(d[3])
                 : "r"(a[0]), "r"(a[1]), "r"(a[2]), "r"(a[3]),
                   "r"(b[0]), "r"(b[1]));
}
DI void ldm4(uint32_t* r, uint32_t addr) {
    asm volatile("ldmatrix.sync.aligned.m8n8.x4.shared.b16 {%0,%1,%2,%3}, [%4];"
                 : "=r"(r[0]), "=r"(r[1]), "=r"(r[2]), "=r"(r[3]) : "r"(addr));
}

// warp tile 64x32, k-chunk 64 = 4 k-steps of m16n8k16: per ks 6 ldmatrix.x4 + 16 mma
DI void compute_chunk16(uint32_t aB, uint32_t bB,
                        const uint32_t* aoff, const uint32_t* boff,
                        float (&d)[4][4][4]) {
#pragma unroll
    for (int ks = 0; ks < KS; ++ks) {
        uint32_t a[4][4], b[2][4];
#pragma unroll
        for (int mt = 0; mt < 4; ++mt) ldm4(a[mt], aB + aoff[mt] + ks * 32);
#pragma unroll
        for (int p = 0; p < 2; ++p)  ldm4(b[p], bB + boff[p] + ks * 32);
#pragma unroll
        for (int mt = 0; mt < 4; ++mt)
#pragma unroll
            for (int p = 0; p < 2; ++p) {
                mma16(d[mt][2 * p],     a[mt], &b[p][0]);
                mma16(d[mt][2 * p + 1], a[mt], &b[p][2]);
            }
    }
}

// A: 16x16 tile per mt. lanes 0-15 -> rows, k-half 0; lanes 16-31 -> rows, k-half 1.
DI void make_aoff(uint32_t* aoff, int warpM, int lane) {
    const int lr = lane & 15, lk = (lane >> 4) & 1;
#pragma unroll
    for (int mt = 0; mt < 4; ++mt)
        aoff[mt] = ((warpM * 64 + mt * 16 + lr) * SROW + lk * 8) * 2;
}
// B: 16(n)x16(k) tile per p. lanes: b3 = k-half, b4 = n-half.
DI void make_boff(uint32_t* boff, int warpN, int lane) {
    const int lr = lane & 7, lk = (lane >> 3) & 1, ln = (lane >> 4) & 1;
#pragma unroll
    for (int p = 0; p < 2; ++p)
        boff[p] = ((warpN * 32 + p * 16 + ln * 8 + lr) * SROW + lk * 8) * 2;
}

// ---------------- input conversion ----------------
__global__ void cvt_x_kernel(const float* __restrict__ x) {
    const size_t i = ((size_t)blockIdx.x * blockDim.x + threadIdx.x) * 4;
    float4 v = *reinterpret_cast<const float4*>(x + i);
    __half2 h01 = __floats2half2_rn(v.x, v.y);
    __half2 h23 = __floats2half2_rn(v.z, v.w);
    uint2 u;
    u.x = *reinterpret_cast<uint32_t*>(&h01);
    u.y = *reinterpret_cast<uint32_t*>(&h23);
    *reinterpret_cast<uint2*>(g_X + i) = u;
}

// ---------------- weight packing ----------------
DI float w1_src(int n, int d, const float* sW1, const float* dW1, const float* gW1) {
    if (n < NSv * H1v) {
        int e = n >> 8, h = n & 255;
        return sW1[((size_t)e * DIMD + d) * H1v + h];
    } else if (n < GCOL) {
        int m = n - NSv * H1v, e = m >> 8, h = m & 255;
        return dW1[((size_t)e * DIMD + d) * H1v + h];
    } else if (n < GCOL + DCv * GHv) {
        int m = n - GCOL, g = m >> 6, k = m & 63;
        return gW1[((size_t)g * DIMD + d) * GHv + k];
    }
    return 0.0f;
}

__global__ void pack_w1_kernel(const float* __restrict__ sW1, const float* __restrict__ dW1,
                               const float* __restrict__ gW1, const float* __restrict__ sb1,
                               const float* __restrict__ db1, const float* __restrict__ gb1) {
    __shared__ float t[32][33];
    const int n0 = blockIdx.x * 32, d0 = blockIdx.y * 32;
    const int tx = threadIdx.x, ty = threadIdx.y;
#pragma unroll
    for (int i = 0; i < 4; ++i)
        t[ty + i * 8][tx] = w1_src(n0 + tx, d0 + ty + i * 8, sW1, dW1, gW1);
    __syncthreads();
#pragma unroll
    for (int i = 0; i < 4; ++i)
        g_Wt1[(size_t)(n0 + ty + i * 8) * DIMD + d0 + tx] = __float2half_rn(t[tx][ty + i * 8]);
    if (blockIdx.y == 0 && ty == 0) {
        int n = n0 + tx;
        float bv;
        if (n < NSv * H1v) bv = sb1[n];
        else if (n < GCOL) bv = db1[n - NSv * H1v];
        else if (n < GCOL + DCv * GHv) bv = gb1[n - GCOL];
        else bv = 0.0f;
        g_b1[n] = bv;
    }
}

__global__ void pack_w2_kernel(const float* __restrict__ sW2, const float* __restrict__ dW2,
                               const float* __restrict__ sb2, const float* __restrict__ db2) {
    __shared__ float t[32][33];
    const int o0 = blockIdx.x * 32, h0 = blockIdx.y * 32, e = blockIdx.z;
    const int tx = threadIdx.x, ty = threadIdx.y;
#pragma unroll
    for (int i = 0; i < 4; ++i) {
        int h = h0 + ty + i * 8, o = o0 + tx;
        float v = (e < NSv) ? sW2[((size_t)e * H1v + h) * H2v + o]
                            : dW2[((size_t)(e - NSv) * H1v + h) * H2v + o];
        t[ty + i * 8][tx] = v;
    }
    __syncthreads();
#pragma unroll
    for (int i = 0; i < 4; ++i) {
        int o = o0 + ty + i * 8, h = h0 + tx;
        g_Wt2[((size_t)e * H2v + o) * H1v + h] = __float2half_rn(t[tx][ty + i * 8]);
    }
    if (blockIdx.y == 0 && ty == 0) {
        int o = o0 + tx;
        g_b2[e * H2v + o] = (e < NSv) ? sb2[e * H2v + o] : db2[(e - NSv) * H2v + o];
    }
}

// ---------------- GEMM1: Y = fp16(relu(X @ W1cat + b1)), 256 thr, 8 warps 64x32, 3-stage, K-chunk 64 ----------------
__global__ void __launch_bounds__(256, 2) gemm1_kernel() {
    extern __shared__ char smem[];
    const uint32_t sbase = smem_u32(smem);
    const int tid = threadIdx.x, wid = tid >> 5, lane = tid & 31;
    const int warpM = wid >> 2, warpN = wid & 3;   // 2 M x 4 N of 64x32
    const int g = lane >> 2, tg = lane & 3;
    const int n0 = blockIdx.x * 128, m0 = blockIdx.y * 128;   // N fastest -> X L2-hot

    uint32_t aoff[4], boff[2];
    make_aoff(aoff, warpM, lane);
    make_boff(boff, warpN, lane);

    float d[4][4][4] = {};

    auto load = [&](int stg, int ck) {
        const __half* xa = g_X + (size_t)m0 * DIMD + ck * KCH;
        const __half* wb = g_Wt1 + (size_t)n0 * DIMD + ck * KCH;
        const uint32_t da = sbase + stg * STAGE_B;
        const uint32_t db = da + HBUF;
#pragma unroll
        for (int it = 0; it < 4; ++it) {
            int idx = tid + it * 256, r = idx >> 3, cc = idx & 7;
            cp16(da + r * 144 + cc * 16, xa + (size_t)r * DIMD + cc * 8);
            cp16(db + r * 144 + cc * 16, wb + (size_t)r * DIMD + cc * 8);
        }
        cp_commit();
    };

    load(0, 0);
    load(1, 1);
    for (int ck = 0; ck < 16; ++ck) {
        cp_wait1();
        __syncthreads();
        if (ck + 2 < 16) load((ck + 2) % NSTG, ck + 2);
        else cp_commit();
        const uint32_t aB = sbase + (ck % NSTG) * STAGE_B;
        compute_chunk16(aB, aB + HBUF, aoff, boff, d);
    }
    __syncthreads();

    float* stage = reinterpret_cast<float*>(smem);
#pragma unroll
    for (int mt = 0; mt < 4; ++mt)
#pragma unroll
        for (int nt = 0; nt < 4; ++nt)
#pragma unroll
            for (int i = 0; i < 4; ++i) {
                int r = warpM * 64 + mt * 16 + g + ((i >= 2) ? 8 : 0);
                int cc = warpN * 32 + nt * 8 + tg * 2 + (i & 1);
                stage[r * STG + cc] = d[mt][nt][i];
            }
    __syncthreads();
    {
        const int cg = tid & 31, r0 = tid >> 5;
        const float4 b4 = *reinterpret_cast<const float4*>(g_b1 + n0 + cg * 4);
#pragma unroll
        for (int p = 0; p < 16; ++p) {
            int r = r0 + p * 8;
            const float* s = stage + r * STG + cg * 4;
            __half2 h01 = __floats2half2_rn(fmaxf(s[0] + b4.x, 0.0f), fmaxf(s[1] + b4.y, 0.0f));
            __half2 h23 = __floats2half2_rn(fmaxf(s[2] + b4.z, 0.0f), fmaxf(s[3] + b4.w, 0.0f));
            uint2 u;
            u.x = *reinterpret_cast<uint32_t*>(&h01);
            u.y = *reinterpret_cast<uint32_t*>(&h23);
            *reinterpret_cast<uint2*>(g_Y + (size_t)(m0 + r) * NCOLS + n0 + cg * 4) = u;
        }
    }
}

// ---------------- gates ----------------
__global__ void __launch_bounds__(256) gate_kernel(const float* __restrict__ gW2,
                                                   const float* __restrict__ gb2) {
    const int gw = (blockIdx.x * blockDim.x + threadIdx.x) >> 5;
    const int lane = threadIdx.x & 31;
    if (gw >= DCv * BATCH) return;
    const int g = gw / BATCH, b = gw % BATCH;
    const __half* yr = g_Y + (size_t)b * NCOLS + GCOL + g * GHv;
    const __half2 h2 = *reinterpret_cast<const __half2*>(yr + 2 * lane);
    const float h0 = __low2float(h2), h1 = __high2float(h2);
    const float* w = gW2 + (size_t)g * GHv * 6;
    float acc[6];
#pragma unroll
    for (int e = 0; e < 6; ++e)
        acc[e] = h0 * w[(2 * lane) * 6 + e] + h1 * w[(2 * lane + 1) * 6 + e];
#pragma unroll
    for (int e = 0; e < 6; ++e)
#pragma unroll
        for (int s = 16; s; s >>= 1) acc[e] += __shfl_xor_sync(0xFFFFFFFFu, acc[e], s);
    if (lane == 0) {
        float m = -1e30f;
#pragma unroll
        for (int e = 0; e < 6; ++e) { acc[e] += gb2[g * 6 + e]; m = fmaxf(m, acc[e]); }
        float s = 0.0f;
#pragma unroll
        for (int e = 0; e < 6; ++e) { acc[e] = expf(acc[e] - m); s += acc[e]; }
        const float inv = 1.0f / s;
#pragma unroll
        for (int e = 0; e < 6; ++e)
            g_gates[((size_t)g * BATCH + b) * 8 + e] = acc[e] * inv;
    }
}

// ---------------- GEMM2: Z[e] = relu(Y_e @ W2_e + b2_e), grid (m, e), 3-stage, K-chunk 64 ----------------
__global__ void __launch_bounds__(256, 2) gemm2_kernel() {
    extern __shared__ char smem[];
    const uint32_t sbase = smem_u32(smem);
    const int tid = threadIdx.x, wid = tid >> 5, lane = tid & 31;
    const int warpM = wid >> 2, warpN = wid & 3;
    const int g = lane >> 2, tg = lane & 3;
    const int m0 = blockIdx.x * 128, e = blockIdx.y;

    uint32_t aoff[4], boff[2];
    make_aoff(aoff, warpM, lane);
    make_boff(boff, warpN, lane);

    float d[4][4][4] = {};

    auto load = [&](int stg, int ck) {
        const __half* ya = g_Y + (size_t)m0 * NCOLS + e * H1v + ck * KCH;
        const __half* wb = g_Wt2 + (size_t)e * H2v * H1v + ck * KCH;
        const uint32_t da = sbase + stg * STAGE_B;
        const uint32_t db = da + HBUF;
#pragma unroll
        for (int it = 0; it < 4; ++it) {
            int ii = tid + it * 256, r = ii >> 3, cc = ii & 7;
            cp16(da + r * 144 + cc * 16, ya + (size_t)r * NCOLS + cc * 8);
            cp16(db + r * 144 + cc * 16, wb + (size_t)r * H1v + cc * 8);
        }
        cp_commit();
    };

    load(0, 0);
    load(1, 1);
    for (int ck = 0; ck < 4; ++ck) {
        cp_wait1();
        __syncthreads();
        if (ck + 2 < 4) load((ck + 2) % NSTG, ck + 2);
        else cp_commit();
        const uint32_t aB = sbase + (ck % NSTG) * STAGE_B;
        compute_chunk16(aB, aB + HBUF, aoff, boff, d);
    }
    __syncthreads();

    float* stage = reinterpret_cast<float*>(smem);
#pragma unroll
    for (int mt = 0; mt < 4; ++mt)
#pragma unroll
        for (int nt = 0; nt < 4; ++nt)
#pragma unroll
            for (int i = 0; i < 4; ++i) {
                int r = warpM * 64 + mt * 16 + g + ((i >= 2) ? 8 : 0);
                int cc = warpN * 32 + nt * 8 + tg * 2 + (i & 1);
                stage[r * STG + cc] = d[mt][nt][i];
            }
    __syncthreads();
    {
        const int cg = tid & 31, r0 = tid >> 5;
        const float4 b4 = *reinterpret_cast<const float4*>(g_b2 + e * H2v + cg * 4);
#pragma unroll
        for (int p = 0; p < 16; ++p) {
            int r = r0 + p * 8;
            const float* s = stage + r * STG + cg * 4;
            float4 v;
            v.x = fmaxf(s[0] + b4.x, 0.0f);
            v.y = fmaxf(s[1] + b4.y, 0.0f);
            v.z = fmaxf(s[2] + b4.z, 0.0f);
            v.w = fmaxf(s[3] + b4.w, 0.0f);
            *reinterpret_cast<float4*>(g_Z + ((size_t)e * BATCH + m0 + r) * H2v + cg * 4) = v;
        }
    }
}

// ---------------- combine ----------------
__global__ void __launch_bounds__(256) combine_kernel(float* __restrict__ out) {
    const int gid = blockIdx.x * blockDim.x + threadIdx.x;
    const int b = gid >> 5, c = (gid & 31) * 4;
    if (b >= BATCH) return;
    float gw[DCv][6];
#pragma unroll
    for (int g = 0; g < DCv; ++g)
#pragma unroll
        for (int e = 0; e < 6; ++e)
            gw[g][e] = g_gates[((size_t)g * BATCH + b) * 8 + e];
    float4 acc[DCv];
#pragma unroll
    for (int g = 0; g < DCv; ++g) acc[g] = make_float4(0.f, 0.f, 0.f, 0.f);
#pragma unroll
    for (int e = 0; e < NEv; ++e) {
        float4 z = *reinterpret_cast<const float4*>(g_Z + ((size_t)e * BATCH + b) * H2v + c);
        if (e < NSv) {
#pragma unroll
            for (int g = 0; g < DCv; ++g) {
                const float w = gw[g][e];
                acc[g].x += w * z.x; acc[g].y += w * z.y;
                acc[g].z += w * z.z; acc[g].w += w * z.w;
            }
        } else {
            const int g = (e - NSv) >> 1;
            const float w = gw[g][NSv + ((e - NSv) & 1)];
            acc[g].x += w * z.x; acc[g].y += w * z.y;
            acc[g].z += w * z.z; acc[g].w += w * z.w;
        }
    }
#pragma unroll
    for (int g = 0; g < DCv; ++g)
        *reinterpret_cast<float4*>(out + ((size_t)g * BATCH + b) * H2v + c) = acc[g];
}

extern "C" void kernel_launch(void* const* d_in, const int* in_sizes, int n_in,
                              void* d_out, int out_size) {
    const float *x, *sW1, *sb1, *sW2, *sb2, *dW1, *db1, *dW2, *db2, *gW1, *gb1, *gW2, *gb2;
    if (n_in >= 14 && in_sizes[1] == BATCH) {
        x   = (const float*)d_in[0];
        sW1 = (const float*)d_in[2];  sb1 = (const float*)d_in[3];
        sW2 = (const float*)d_in[4];  sb2 = (const float*)d_in[5];
        dW1 = (const float*)d_in[6];  db1 = (const float*)d_in[7];
        dW2 = (const float*)d_in[8];  db2 = (const float*)d_in[9];
        gW1 = (const float*)d_in[10]; gb1 = (const float*)d_in[11];
        gW2 = (const float*)d_in[12]; gb2 = (const float*)d_in[13];
    } else {
        x   = (const float*)d_in[0];
        sW1 = (const float*)d_in[1];  sb1 = (const float*)d_in[2];
        sW2 = (const float*)d_in[3];  sb2 = (const float*)d_in[4];
        dW1 = (const float*)d_in[5];  db1 = (const float*)d_in[6];
        dW2 = (const float*)d_in[7];  db2 = (const float*)d_in[8];
        gW1 = (const float*)d_in[9];  gb1 = (const float*)d_in[10];
        gW2 = (const float*)d_in[11]; gb2 = (const float*)d_in[12];
    }
    float* out = (float*)d_out;

    cudaFuncSetAttribute(gemm1_kernel, cudaFuncAttributeMaxDynamicSharedMemorySize, SMEM_TOT);
    cudaFuncSetAttribute(gemm2_kernel, cudaFuncAttributeMaxDynamicSharedMemorySize, SMEM_TOT);

    cvt_x_kernel<<<(BATCH * DIMD / 4) / 256, 256>>>(x);
    pack_w1_kernel<<<dim3(NCOLS / 32, DIMD / 32), dim3(32, 8)>>>(sW1, dW1, gW1, sb1, db1, gb1);
    pack_w2_kernel<<<dim3(H2v / 32, H1v / 32, NEv), dim3(32, 8)>>>(sW2, dW2, sb2, db2);
    gemm1_kernel<<<dim3(NCOLS / 128, BATCH / 128), 256, SMEM_TOT>>>();
    gate_kernel<<<(DCv * BATCH) / 8, 256>>>(gW2, gb2);
    gemm2_kernel<<<dim3(BATCH / 128, NEv), 256, SMEM_TOT>>>();
    combine_kernel<<<(BATCH * 32) / 256, 256>>>(out);
}